// round 13
// baseline (speedup 1.0000x reference)
#include <cuda_runtime.h>
#include <cuda_fp16.h>
#include <mma.h>
#include <math.h>

using namespace nvcuda;

#define NN 8192
#define EE 262144
#define DIN 256
#define HID 64

// ---------------- scratch (device globals; no allocation allowed) ----------------
static __device__ __half g_S[(size_t)2 * NN * NN];         // 268 MB fp16 unnormalized exp scores
static __device__ float g_h1[NN * 128];
static __device__ float g_ht1[NN * 128];
static __device__ float g_h2[NN * 64];
static __device__ float g_htkg[NN * 64];
static __device__ float g_as1[NN * 2], g_ad1[NN * 2];
static __device__ float g_as2[NN], g_ad2[NN];
static __device__ float g_dinv[NN];
static __device__ float g_g1[NN * 64], g_he1[NN * 64];
static __device__ float g_g2[NN * 64], g_hekg[NN * 64];
static __device__ float g_q[NN * 64], g_k[NN * 64], g_v[NN * 64];
static __device__ __half g_qh[NN * 64], g_kh[NN * 64], g_vh[NN * 64];
static __device__ float g_attnout[NN * 64];
static __device__ float g_t1[NN * 64];
static __device__ float g_qn[NN * 2];
static __device__ float g_knm[2];
static __device__ float g_dsum[NN * 2];
static __device__ float g_bcomb[128 * 64];   // [fc1_W_top ; Wo@fc1_W_bot]
static __device__ float g_bfold[64];         // bo@fc1_W_bot + fc1_b
// CSR scratch (two graphs)
static __device__ int g_cnt_t[NN], g_cur_t[NN], g_off_t[NN + 1], g_srcs_t[EE];
static __device__ int g_cnt_e[NN], g_cur_e[NN], g_off_e[NN + 1], g_srcs_e[EE];

// ---------------- helpers ----------------
__device__ __forceinline__ void atomicMaxF(float* addr, float v) {
    if (v >= 0.f) atomicMax((int*)addr, __float_as_int(v));
    else          atomicMin((unsigned int*)addr, __float_as_uint(v));
}

__device__ __forceinline__ float leaky(float x) { return (x >= 0.f) ? x : 0.2f * x; }

// ---------------- fold Wo into fc1 (weights only; off critical path) ----------------
// Bcomb[0:64]   = fc1_W[0:64]                 (top half, passthrough for h_tkg)
// Bcomb[64:128] = Wo @ fc1_W[64:128]          (folded projection for attnout)
// bfold         = bo @ fc1_W[64:128] + fc1_b
__global__ void fold_kernel(const float* __restrict__ Wo, const float* __restrict__ bo,
                            const float* __restrict__ fc1_W, const float* __restrict__ fc1_b,
                            float* __restrict__ Bcomb, float* __restrict__ bfold) {
    int i = blockIdx.x * blockDim.x + threadIdx.x;
    if (i < 4096) {
        Bcomb[i] = fc1_W[i];
    } else if (i < 8192) {
        int j = i - 4096;
        int r = j >> 6, c = j & 63;
        float s = 0.f;
#pragma unroll 8
        for (int k = 0; k < 64; k++) s = fmaf(Wo[r * 64 + k], fc1_W[(64 + k) * 64 + c], s);
        Bcomb[4096 + j] = s;
    } else if (i < 8256) {
        int c = i - 8192;
        float s = fc1_b[c];
#pragma unroll 8
        for (int k = 0; k < 64; k++) s = fmaf(bo[k], fc1_W[(64 + k) * 64 + c], s);
        bfold[c] = s;
    }
}

// ---------------- CSR build ----------------
__global__ void hist_kernel(const int* __restrict__ ei, int* cnt) {
    int e = blockIdx.x * blockDim.x + threadIdx.x;
    if (e < EE) atomicAdd(&cnt[ei[EE + e]], 1);
}

__global__ __launch_bounds__(1024) void scan_kernel(const int* __restrict__ cnt, int* __restrict__ off) {
    __shared__ int sm[1024];
    int tid = threadIdx.x;
    int base = tid * 8;
    int local[8];
    int s = 0;
#pragma unroll
    for (int j = 0; j < 8; j++) { local[j] = s; s += cnt[base + j]; }
    sm[tid] = s;
    __syncthreads();
    for (int d = 1; d < 1024; d <<= 1) {
        int v = (tid >= d) ? sm[tid - d] : 0;
        __syncthreads();
        sm[tid] += v;
        __syncthreads();
    }
    int pre = (tid == 0) ? 0 : sm[tid - 1];
#pragma unroll
    for (int j = 0; j < 8; j++) off[base + j] = pre + local[j];
    if (tid == 1023) off[NN] = sm[1023];
}

__global__ void scatter_kernel(const int* __restrict__ ei, const int* __restrict__ off,
                               int* cur, int* __restrict__ srcs) {
    int e = blockIdx.x * blockDim.x + threadIdx.x;
    if (e >= EE) return;
    int d = ei[EE + e];
    int p = off[d] + atomicAdd(&cur[d], 1);
    srcs[p] = ei[e];
}

__global__ void dinv_kernel(const int* __restrict__ cnt, float* dinv) {
    int i = blockIdx.x * blockDim.x + threadIdx.x;
    if (i < NN) dinv[i] = rsqrtf((float)(cnt[i] + 1));
}

// ---------------- generic tiled GEMM: C = act(A[M,K] @ B[K,N] + bias) ----------------
// A2 != null: logical A = [A | A2], each K/2 wide, row stride K/2 (fused concat).
// Ch != null: fp16 mirror of C.
// mode: 0 none
//       1 GAT alpha: out1/out2[m*H+head] = row_head . att_s/att_d  (head = n0>>6)
//       2 qnorm: out1[m*2+head] = ||row_head||       (N==64, heads of 32)
//       3 knorm: atomicMax(out1[head], ||row_head||) (N==64, heads of 32)
__global__ __launch_bounds__(256) void gemm64(const float* __restrict__ A,
                                              const float* __restrict__ A2,
                                              const float* __restrict__ B,
                                              const float* __restrict__ bias,
                                              float* __restrict__ C,
                                              __half* __restrict__ Ch,
                                              int M, int N, int K, int act,
                                              int mode,
                                              const float* __restrict__ att_s,
                                              const float* __restrict__ att_d,
                                              float* __restrict__ out1,
                                              float* __restrict__ out2,
                                              int H) {
    __shared__ float As[16][65];
    __shared__ float Bs[16][64];
    int tid = threadIdx.x;
    int tx = tid & 15, ty = tid >> 4;
    int m0 = blockIdx.y * 64, n0 = blockIdx.x * 64;
    float acc[4][4] = {};
    for (int k0 = 0; k0 < K; k0 += 16) {
        {
            int r = tid >> 2, c = (tid & 3) * 4;
            const float* src;
            if (A2 == nullptr) {
                src = A + (size_t)(m0 + r) * K + k0 + c;
            } else {
                int kk = k0 + c, half = K >> 1;
                src = (kk < half) ? (A  + (size_t)(m0 + r) * half + kk)
                                  : (A2 + (size_t)(m0 + r) * half + kk - half);
            }
            float4 av = *(const float4*)src;
            As[c + 0][r] = av.x; As[c + 1][r] = av.y; As[c + 2][r] = av.z; As[c + 3][r] = av.w;
        }
        {
            int r = tid >> 4, c = (tid & 15) * 4;
            float4 bv = *(const float4*)(B + (size_t)(k0 + r) * N + n0 + c);
            *(float4*)&Bs[r][c] = bv;
        }
        __syncthreads();
#pragma unroll
        for (int kk = 0; kk < 16; kk++) {
            float a[4], b[4];
#pragma unroll
            for (int i = 0; i < 4; i++) a[i] = As[kk][ty * 4 + i];
            float4 bv = *(float4*)&Bs[kk][tx * 4];
            b[0] = bv.x; b[1] = bv.y; b[2] = bv.z; b[3] = bv.w;
#pragma unroll
            for (int i = 0; i < 4; i++)
#pragma unroll
                for (int j = 0; j < 4; j++) acc[i][j] = fmaf(a[i], b[j], acc[i][j]);
        }
        __syncthreads();
    }
#pragma unroll
    for (int i = 0; i < 4; i++) {
        int m = m0 + ty * 4 + i;
        float v[4];
#pragma unroll
        for (int j = 0; j < 4; j++) {
            v[j] = acc[i][j];
            if (bias) v[j] += bias[n0 + tx * 4 + j];
        }
        if (mode == 1) {
            int head = n0 >> 6;
            float ss = 0.f, dd = 0.f;
#pragma unroll
            for (int j = 0; j < 4; j++) {
                int n = n0 + tx * 4 + j;
                ss = fmaf(v[j], att_s[n], ss);
                dd = fmaf(v[j], att_d[n], dd);
            }
#pragma unroll
            for (int o = 8; o > 0; o >>= 1) {
                ss += __shfl_down_sync(0xffffffffu, ss, o, 16);
                dd += __shfl_down_sync(0xffffffffu, dd, o, 16);
            }
            if (tx == 0) { out1[m * H + head] = ss; out2[m * H + head] = dd; }
        } else if (mode == 2 || mode == 3) {
            int head = tx >> 3;
            float sq = 0.f;
#pragma unroll
            for (int j = 0; j < 4; j++) sq = fmaf(v[j], v[j], sq);
#pragma unroll
            for (int o = 4; o > 0; o >>= 1) sq += __shfl_down_sync(0xffffffffu, sq, o, 8);
            if ((tx & 7) == 0) {
                if (mode == 2) out1[m * 2 + head] = sqrtf(sq);
                else           atomicMaxF(&out1[head], sqrtf(sq));
            }
        }
#pragma unroll
        for (int j = 0; j < 4; j++) {
            int n = n0 + tx * 4 + j;
            float w = v[j];
            if (act == 1) w = fmaxf(w, 0.f);
            else if (act == 2) w = (w > 0.f) ? w : expm1f(w);
            C[(size_t)m * N + n] = w;
            if (Ch) Ch[(size_t)m * N + n] = __float2half(w);
        }
    }
}

// ---------------- GAT: one warp per (dst, head), CSR gather, softmax in regs, bias+ELU ----------------
__global__ void gat_aggr_csr(const int* __restrict__ off, const int* __restrict__ srcs,
                             const float* __restrict__ as_, const float* __restrict__ ad_,
                             const float* __restrict__ hfeat, const float* __restrict__ bias,
                             float* __restrict__ out, int H) {
    int w = (blockIdx.x * blockDim.x + threadIdx.x) >> 5;
    int lane = threadIdx.x & 31;
    if (w >= NN * H) return;
    int d = w / H, hh = w - d * H;
    int beg = off[d], end = off[d + 1];
    float adv = ad_[w];
    float selfx = leaky(as_[w] + adv);
    float m = selfx;
    for (int i = beg + lane; i < end; i += 32)
        m = fmaxf(m, leaky(__ldg(&as_[srcs[i] * H + hh]) + adv));
#pragma unroll
    for (int o = 16; o > 0; o >>= 1) m = fmaxf(m, __shfl_xor_sync(0xffffffffu, m, o));
    float ssum = (lane == 0) ? __expf(selfx - m) : 0.f;
    for (int i = beg + lane; i < end; i += 32)
        ssum += __expf(leaky(__ldg(&as_[srcs[i] * H + hh]) + adv) - m);
#pragma unroll
    for (int o = 16; o > 0; o >>= 1) ssum += __shfl_xor_sync(0xffffffffu, ssum, o);
    float inv = 1.0f / (ssum + 1e-16f);
    int stride = H * HID;
    int fo = hh * HID;
    float alf = __expf(selfx - m) * inv;
    float a0 = alf * hfeat[(size_t)d * stride + fo + lane];
    float a1 = alf * hfeat[(size_t)d * stride + fo + lane + 32];
    int i = beg;
    for (; i + 1 < end; i += 2) {
        int s0 = srcs[i], s1 = srcs[i + 1];
        float x0 = leaky(__ldg(&as_[s0 * H + hh]) + adv);
        float x1 = leaky(__ldg(&as_[s1 * H + hh]) + adv);
        float al0 = __expf(x0 - m) * inv;
        float al1 = __expf(x1 - m) * inv;
        const float* h0 = hfeat + (size_t)s0 * stride + fo;
        const float* h1 = hfeat + (size_t)s1 * stride + fo;
        a0 = fmaf(al0, h0[lane], a0);
        a1 = fmaf(al0, h0[lane + 32], a1);
        a0 = fmaf(al1, h1[lane], a0);
        a1 = fmaf(al1, h1[lane + 32], a1);
    }
    if (i < end) {
        int s = srcs[i];
        float xx = leaky(__ldg(&as_[s * H + hh]) + adv);
        float al = __expf(xx - m) * inv;
        const float* hs = hfeat + (size_t)s * stride + fo;
        a0 = fmaf(al, hs[lane], a0);
        a1 = fmaf(al, hs[lane + 32], a1);
    }
    float v0 = a0 + bias[fo + lane];
    float v1 = a1 + bias[fo + lane + 32];
    v0 = (v0 > 0.f) ? v0 : expm1f(v0);   // ELU
    v1 = (v1 > 0.f) ? v1 : expm1f(v1);
    out[(size_t)d * stride + fo + lane] = v0;
    out[(size_t)d * stride + fo + lane + 32] = v1;
}

// ---------------- GCN: one warp per dst, CSR gather, fused bias+ReLU ----------------
__global__ void gcn_aggr_csr(const int* __restrict__ off, const int* __restrict__ srcs,
                             const float* __restrict__ hg, const float* __restrict__ dinv,
                             const float* __restrict__ bias, float* __restrict__ out) {
    int w = (blockIdx.x * blockDim.x + threadIdx.x) >> 5;
    int lane = threadIdx.x & 31;
    if (w >= NN) return;
    int d = w;
    int beg = off[d], end = off[d + 1];
    float dv = dinv[d];
    float a0 = dv * hg[(size_t)d * 64 + lane];
    float a1 = dv * hg[(size_t)d * 64 + lane + 32];
    int i = beg;
    for (; i + 1 < end; i += 2) {
        int s0 = srcs[i], s1 = srcs[i + 1];
        float ds0 = __ldg(&dinv[s0]);
        float ds1 = __ldg(&dinv[s1]);
        const float* h0 = hg + (size_t)s0 * 64;
        const float* h1 = hg + (size_t)s1 * 64;
        a0 = fmaf(ds0, h0[lane], a0);
        a1 = fmaf(ds0, h0[lane + 32], a1);
        a0 = fmaf(ds1, h1[lane], a0);
        a1 = fmaf(ds1, h1[lane + 32], a1);
    }
    if (i < end) {
        int s = srcs[i];
        float ds = __ldg(&dinv[s]);
        const float* hs = hg + (size_t)s * 64;
        a0 = fmaf(ds, hs[lane], a0);
        a1 = fmaf(ds, hs[lane + 32], a1);
    }
    float v0 = fmaf(dv, a0, bias[lane]);
    float v1 = fmaf(dv, a1, bias[lane + 32]);
    out[(size_t)d * 64 + lane] = fmaxf(v0, 0.f);
    out[(size_t)d * 64 + lane + 32] = fmaxf(v1, 0.f);
}

// ---------------- attention ----------------
// E[h][q][k] = exp(scale*(q.k - ||q||*knm)) via HMMA; fp16 store; fp32 row sums -> dsum.
__global__ __launch_bounds__(256) void qk_exp_wmma(const __half* __restrict__ Qh,
                                                   const __half* __restrict__ Kh,
                                                   const float* __restrict__ qn,
                                                   const float* __restrict__ knm,
                                                   __half* __restrict__ S,
                                                   float* __restrict__ dsum) {
    __shared__ __align__(32) char buf[36864];
    __half* Qs = (__half*)buf;                 // [64][40]
    __half* Ks = (__half*)(buf + 5120);        // [128][40]
    float* stage = (float*)buf;                // overlay after sync: [8][32*36]
    int h = blockIdx.z;
    int q0 = blockIdx.y * 64, k0 = blockIdx.x * 128;
    int tid = threadIdx.x, wid = tid >> 5, lane = tid & 31;
    {
        int r = tid >> 2, c8 = (tid & 3) * 8;
        *(uint4*)&Qs[r * 40 + c8] = *(const uint4*)(Qh + (size_t)(q0 + r) * 64 + h * 32 + c8);
    }
#pragma unroll
    for (int i = 0; i < 2; i++) {
        int idx = tid + i * 256;
        int r = idx >> 2, c8 = (idx & 3) * 8;
        *(uint4*)&Ks[r * 40 + c8] = *(const uint4*)(Kh + (size_t)(k0 + r) * 64 + h * 32 + c8);
    }
    __syncthreads();
    int qsub = (wid >> 2) * 32, ksub = (wid & 3) * 32;
    wmma::fragment<wmma::accumulator, 16, 16, 16, float> acc[2][2];
#pragma unroll
    for (int mi = 0; mi < 2; mi++)
#pragma unroll
        for (int ni = 0; ni < 2; ni++) wmma::fill_fragment(acc[mi][ni], 0.0f);
#pragma unroll
    for (int ks = 0; ks < 2; ks++) {
        wmma::fragment<wmma::matrix_a, 16, 16, 16, __half, wmma::row_major> a[2];
        wmma::fragment<wmma::matrix_b, 16, 16, 16, __half, wmma::col_major> b[2];
#pragma unroll
        for (int mi = 0; mi < 2; mi++)
            wmma::load_matrix_sync(a[mi], &Qs[(qsub + mi * 16) * 40 + ks * 16], 40);
#pragma unroll
        for (int ni = 0; ni < 2; ni++)
            wmma::load_matrix_sync(b[ni], &Ks[(ksub + ni * 16) * 40 + ks * 16], 40);
#pragma unroll
        for (int mi = 0; mi < 2; mi++)
#pragma unroll
            for (int ni = 0; ni < 2; ni++)
                wmma::mma_sync(acc[mi][ni], a[mi], b[ni], acc[mi][ni]);
    }
    __syncthreads();
    float* wst = stage + wid * (32 * 36);
#pragma unroll
    for (int mi = 0; mi < 2; mi++)
#pragma unroll
        for (int ni = 0; ni < 2; ni++)
            wmma::store_matrix_sync(&wst[mi * 16 * 36 + ni * 16], acc[mi][ni], 36, wmma::mem_row_major);
    const float sc = 0.17677669529663687f;   // 1/sqrt(32)
    int q = q0 + qsub + lane;
    float shiftsc = qn[q * 2 + h] * knm[h] * sc;
    const float* sp = &wst[lane * 36];
    float rs = 0.f;
    __half2 hv[16];
#pragma unroll
    for (int j = 0; j < 16; j++) {
        float e0 = __expf(fmaf(sp[2 * j], sc, -shiftsc));
        float e1 = __expf(fmaf(sp[2 * j + 1], sc, -shiftsc));
        hv[j] = __floats2half2_rn(e0, e1);
        rs += e0 + e1;
    }
    __half* Sp = S + (size_t)h * NN * NN + (size_t)q * NN + k0 + ksub;
#pragma unroll
    for (int t = 0; t < 4; t++) __stcs((uint4*)(Sp + t * 8), *(uint4*)&hv[t * 4]);
    atomicAdd(&dsum[q * 2 + h], rs);
}

// out[q, h*32+c] += sum_k (E/dsum)*V; streams head-averaged normalized weights.
// k-chunk 64; k-split 8.
__global__ __launch_bounds__(256) void av_wmma(const __half* __restrict__ Sh,
                                               const __half* __restrict__ Vh,
                                               const float* __restrict__ dsum,
                                               float* __restrict__ out,
                                               float* __restrict__ avg) {
    __shared__ __align__(32) char buf[46080];
    __half* E0s = (__half*)buf;                // [128][72]
    __half* E1s = (__half*)(buf + 18432);      // [128][72]
    __half* Vs  = (__half*)(buf + 36864);      // [64][72]
    float* stage = (float*)buf;                // overlay at end: [8][32*36]
    __shared__ float invd[256];
    int q0 = blockIdx.x * 128;
    int kbase = blockIdx.y * 1024;
    int tid = threadIdx.x, wid = tid >> 5, lane = tid & 31;
    if (tid < 128) invd[tid] = 1.0f / dsum[(q0 + tid) * 2];
    else           invd[tid] = 1.0f / dsum[(q0 + tid - 128) * 2 + 1];
    int hh = wid >> 2, qsub = (wid & 3) * 32;
    wmma::fragment<wmma::accumulator, 16, 16, 16, float> acc[2][2];
#pragma unroll
    for (int mi = 0; mi < 2; mi++)
#pragma unroll
        for (int ni = 0; ni < 2; ni++) wmma::fill_fragment(acc[mi][ni], 0.0f);
    for (int kc = 0; kc < 1024; kc += 64) {
        __syncthreads();
#pragma unroll
        for (int i = 0; i < 4; i++) {
            int idx = tid + i * 256;
            int r = idx >> 3, c8 = (idx & 7) * 8;
            size_t goff = (size_t)(q0 + r) * NN + kbase + kc + c8;
            uint4 u0 = __ldcs((const uint4*)(Sh + goff));
            uint4 u1 = __ldcs((const uint4*)(Sh + (size_t)NN * NN + goff));
            *(uint4*)&E0s[r * 72 + c8] = u0;
            *(uint4*)&E1s[r * 72 + c8] = u1;
            float i0 = invd[r], i1 = invd[128 + r];
            __half2* a0 = (__half2*)&u0;
            __half2* a1 = (__half2*)&u1;
            float av8[8];
#pragma unroll
            for (int j = 0; j < 4; j++) {
                float2 f0 = __half22float2(a0[j]);
                float2 f1 = __half22float2(a1[j]);
                av8[2 * j]     = 0.5f * (f0.x * i0 + f1.x * i1);
                av8[2 * j + 1] = 0.5f * (f0.y * i0 + f1.y * i1);
            }
            __stcs((float4*)(avg + goff), *(float4*)&av8[0]);
            __stcs((float4*)(avg + goff + 4), *(float4*)&av8[4]);
        }
#pragma unroll
        for (int i = 0; i < 2; i++) {
            int idx = tid + i * 256;
            int r = idx >> 3, c8 = (idx & 7) * 8;
            *(uint4*)&Vs[r * 72 + c8] = *(const uint4*)(Vh + (size_t)(kbase + kc + r) * 64 + c8);
        }
        __syncthreads();
        __half* Es = hh ? E1s : E0s;
#pragma unroll
        for (int ks = 0; ks < 4; ks++) {
            wmma::fragment<wmma::matrix_a, 16, 16, 16, __half, wmma::row_major> a[2];
            wmma::fragment<wmma::matrix_b, 16, 16, 16, __half, wmma::row_major> b[2];
#pragma unroll
            for (int mi = 0; mi < 2; mi++)
                wmma::load_matrix_sync(a[mi], &Es[(qsub + mi * 16) * 72 + ks * 16], 72);
#pragma unroll
            for (int ni = 0; ni < 2; ni++)
                wmma::load_matrix_sync(b[ni], &Vs[(ks * 16) * 72 + hh * 32 + ni * 16], 72);
#pragma unroll
            for (int mi = 0; mi < 2; mi++)
#pragma unroll
                for (int ni = 0; ni < 2; ni++)
                    wmma::mma_sync(acc[mi][ni], a[mi], b[ni], acc[mi][ni]);
        }
    }
    __syncthreads();
    float* wst = stage + wid * (32 * 36);
#pragma unroll
    for (int mi = 0; mi < 2; mi++)
#pragma unroll
        for (int ni = 0; ni < 2; ni++)
            wmma::store_matrix_sync(&wst[mi * 16 * 36 + ni * 16], acc[mi][ni], 36, wmma::mem_row_major);
    int q = q0 + qsub + lane;
    float invq = invd[hh * 128 + qsub + lane];
    const float* sp = &wst[lane * 36];
#pragma unroll
    for (int j = 0; j < 32; j++)
        atomicAdd(&out[(size_t)q * 64 + hh * 32 + j], sp[j] * invq);
}

// ---------------- misc tail ----------------
__global__ void fc2_kernel(const float* __restrict__ t, const float* __restrict__ W,
                           const float* __restrict__ b, float* __restrict__ pred) {
    int w = (blockIdx.x * blockDim.x + threadIdx.x) >> 5;
    int lane = threadIdx.x & 31;
    if (w >= NN) return;
    float s = t[(size_t)w * 64 + lane] * W[lane] + t[(size_t)w * 64 + lane + 32] * W[lane + 32];
#pragma unroll
    for (int off = 16; off > 0; off >>= 1) s += __shfl_down_sync(0xffffffffu, s, off);
    if (lane == 0) pred[w] = s + b[0];
}

// ---------------- launch ----------------
extern "C" void kernel_launch(void* const* d_in, const int* in_sizes, int n_in,
                              void* d_out, int out_size) {
    const float* x       = (const float*)d_in[0];
    const int*   eit     = (const int*)d_in[1];
    const int*   eie     = (const int*)d_in[2];
    const float* gat1_W  = (const float*)d_in[3];
    const float* gat1_as = (const float*)d_in[4];
    const float* gat1_ad = (const float*)d_in[5];
    const float* gat1_b  = (const float*)d_in[6];
    const float* gat2_W  = (const float*)d_in[7];
    const float* gat2_as = (const float*)d_in[8];
    const float* gat2_ad = (const float*)d_in[9];
    const float* gat2_b  = (const float*)d_in[10];
    const float* gcn1_W  = (const float*)d_in[11];
    const float* gcn1_b  = (const float*)d_in[12];
    const float* gcn2_W  = (const float*)d_in[13];
    const float* gcn2_b  = (const float*)d_in[14];
    const float* Wq = (const float*)d_in[15]; const float* bq = (const float*)d_in[16];
    const float* Wk = (const float*)d_in[17]; const float* bk = (const float*)d_in[18];
    const float* Wv = (const float*)d_in[19]; const float* bv = (const float*)d_in[20];
    const float* Wo = (const float*)d_in[21]; const float* bo = (const float*)d_in[22];
    const float* fc1_W = (const float*)d_in[23]; const float* fc1_b = (const float*)d_in[24];
    const float* fc2_W = (const float*)d_in[25]; const float* fc2_b = (const float*)d_in[26];

    float* out_pred = (float*)d_out;
    float* out_attn = (float*)d_out + NN;

    __half *pS, *pqh, *pkh, *pvh;
    float *ph1, *pht1, *ph2, *phtkg, *pas1, *pad1, *pas2, *pad2;
    float *pdinv, *pg1, *phe1, *pg2, *phekg;
    float *pq, *pk, *pv, *pao, *pt1, *pqn, *pknm, *pdsum, *pbcomb, *pbfold;
    int *pcnt_t, *pcur_t, *poff_t, *psrcs_t, *pcnt_e, *pcur_e, *poff_e, *psrcs_e;
    cudaGetSymbolAddress((void**)&pS, g_S);
    cudaGetSymbolAddress((void**)&pqh, g_qh);    cudaGetSymbolAddress((void**)&pkh, g_kh);
    cudaGetSymbolAddress((void**)&pvh, g_vh);
    cudaGetSymbolAddress((void**)&ph1, g_h1);    cudaGetSymbolAddress((void**)&pht1, g_ht1);
    cudaGetSymbolAddress((void**)&ph2, g_h2);    cudaGetSymbolAddress((void**)&phtkg, g_htkg);
    cudaGetSymbolAddress((void**)&pas1, g_as1);  cudaGetSymbolAddress((void**)&pad1, g_ad1);
    cudaGetSymbolAddress((void**)&pas2, g_as2);  cudaGetSymbolAddress((void**)&pad2, g_ad2);
    cudaGetSymbolAddress((void**)&pdinv, g_dinv);
    cudaGetSymbolAddress((void**)&pg1, g_g1);    cudaGetSymbolAddress((void**)&phe1, g_he1);
    cudaGetSymbolAddress((void**)&pg2, g_g2);    cudaGetSymbolAddress((void**)&phekg, g_hekg);
    cudaGetSymbolAddress((void**)&pq, g_q);      cudaGetSymbolAddress((void**)&pk, g_k);
    cudaGetSymbolAddress((void**)&pv, g_v);      cudaGetSymbolAddress((void**)&pao, g_attnout);
    cudaGetSymbolAddress((void**)&pt1, g_t1);
    cudaGetSymbolAddress((void**)&pqn, g_qn);    cudaGetSymbolAddress((void**)&pknm, g_knm);
    cudaGetSymbolAddress((void**)&pdsum, g_dsum);
    cudaGetSymbolAddress((void**)&pbcomb, g_bcomb); cudaGetSymbolAddress((void**)&pbfold, g_bfold);
    cudaGetSymbolAddress((void**)&pcnt_t, g_cnt_t); cudaGetSymbolAddress((void**)&pcur_t, g_cur_t);
    cudaGetSymbolAddress((void**)&poff_t, g_off_t); cudaGetSymbolAddress((void**)&psrcs_t, g_srcs_t);
    cudaGetSymbolAddress((void**)&pcnt_e, g_cnt_e); cudaGetSymbolAddress((void**)&pcur_e, g_cur_e);
    cudaGetSymbolAddress((void**)&poff_e, g_off_e); cudaGetSymbolAddress((void**)&psrcs_e, g_srcs_e);

    static cudaStream_t s1 = nullptr, s2 = nullptr;
    static cudaEvent_t evRoot = nullptr, evT = nullptr, evB = nullptr;
    if (!s1) {
        cudaStreamCreateWithFlags(&s1, cudaStreamNonBlocking);
        cudaStreamCreateWithFlags(&s2, cudaStreamNonBlocking);
        cudaEventCreateWithFlags(&evRoot, cudaEventDisableTiming);
        cudaEventCreateWithFlags(&evT, cudaEventDisableTiming);
        cudaEventCreateWithFlags(&evB, cudaEventDisableTiming);
    }

    const int T = 256;
    const int EB = (EE + T - 1) / T;

    // ===== fork =====
    cudaEventRecord(evRoot, 0);
    cudaStreamWaitEvent(s1, evRoot, 0);
    cudaStreamWaitEvent(s2, evRoot, 0);

    // ----- s1: CSR for TKG graph -----
    cudaMemsetAsync(pcnt_t, 0, NN * sizeof(int), s1);
    cudaMemsetAsync(pcur_t, 0, NN * sizeof(int), s1);
    hist_kernel<<<EB, T, 0, s1>>>(eit, pcnt_t);
    scan_kernel<<<1, 1024, 0, s1>>>(pcnt_t, poff_t);
    scatter_kernel<<<EB, T, 0, s1>>>(eit, poff_t, pcur_t, psrcs_t);
    cudaEventRecord(evT, s1);

    // ----- s2: fold(Wo->fc1) + CSR EKG + GCN branch + K/V projections (+k-norms) -----
    fold_kernel<<<33, T, 0, s2>>>(Wo, bo, fc1_W, fc1_b, pbcomb, pbfold);
    cudaMemsetAsync(pcnt_e, 0, NN * sizeof(int), s2);
    cudaMemsetAsync(pcur_e, 0, NN * sizeof(int), s2);
    cudaMemsetAsync(pknm, 0, 2 * sizeof(float), s2);
    hist_kernel<<<EB, T, 0, s2>>>(eie, pcnt_e);
    scan_kernel<<<1, 1024, 0, s2>>>(pcnt_e, poff_e);
    scatter_kernel<<<EB, T, 0, s2>>>(eie, poff_e, pcur_e, psrcs_e);
    dinv_kernel<<<(NN + T - 1) / T, T, 0, s2>>>(pcnt_e, pdinv);
    gemm64<<<dim3(1, 128), 256, 0, s2>>>(x, nullptr, gcn1_W, nullptr, pg1, nullptr, NN, 64, DIN, 0,
                                         0, nullptr, nullptr, nullptr, nullptr, 0);
    gcn_aggr_csr<<<(NN * 32 + T - 1) / T, T, 0, s2>>>(poff_e, psrcs_e, pg1, pdinv, gcn1_b, phe1);
    gemm64<<<dim3(1, 128), 256, 0, s2>>>(phe1, nullptr, gcn2_W, nullptr, pg2, nullptr, NN, 64, 64, 0,
                                         0, nullptr, nullptr, nullptr, nullptr, 0);
    gcn_aggr_csr<<<(NN * 32 + T - 1) / T, T, 0, s2>>>(poff_e, psrcs_e, pg2, pdinv, gcn2_b, phekg);
    gemm64<<<dim3(1, 128), 256, 0, s2>>>(phekg, nullptr, Wk, bk, pk, pkh, NN, 64, 64, 0,
                                         3, nullptr, nullptr, pknm, nullptr, 0);
    gemm64<<<dim3(1, 128), 256, 0, s2>>>(phekg, nullptr, Wv, bv, pv, pvh, NN, 64, 64, 0,
                                         0, nullptr, nullptr, nullptr, nullptr, 0);
    cudaEventRecord(evB, s2);

    // ----- s0: GAT branch (critical path) -----
    gemm64<<<dim3(2, 128), 256>>>(x, nullptr, gat1_W, nullptr, ph1, nullptr, NN, 128, DIN, 0,
                                  1, gat1_as, gat1_ad, pas1, pad1, 2);
    cudaStreamWaitEvent(0, evT, 0);
    gat_aggr_csr<<<(NN * 2 * 32 + T - 1) / T, T>>>(poff_t, psrcs_t, pas1, pad1, ph1, gat1_b, pht1, 2);
    gemm64<<<dim3(1, 128), 256>>>(pht1, nullptr, gat2_W, nullptr, ph2, nullptr, NN, 64, 128, 0,
                                  1, gat2_as, gat2_ad, pas2, pad2, 1);
    gat_aggr_csr<<<(NN * 32 + T - 1) / T, T>>>(poff_t, psrcs_t, pas2, pad2, ph2, gat2_b, phtkg, 1);
    gemm64<<<dim3(1, 128), 256>>>(phtkg, nullptr, Wq, bq, pq, pqh, NN, 64, 64, 0,
                                  2, nullptr, nullptr, pqn, nullptr, 0);
    cudaMemsetAsync(pdsum, 0, NN * 2 * sizeof(float));
    cudaMemsetAsync(pao, 0, (size_t)NN * 64 * sizeof(float));
    cudaStreamWaitEvent(0, evB, 0);
    qk_exp_wmma<<<dim3(64, 128, 2), 256>>>(pqh, pkh, pqn, pknm, pS, pdsum);
    av_wmma<<<dim3(64, 8), 256>>>(pS, pvh, pdsum, pao, out_attn);
    gemm64<<<dim3(1, 128), 256>>>(phtkg, pao, pbcomb, pbfold, pt1, nullptr, NN, 64, 128, 1,
                                  0, nullptr, nullptr, nullptr, nullptr, 0);
    fc2_kernel<<<(NN * 32 + T - 1) / T, T>>>(pt1, fc2_W, fc2_b, out_pred);
}

// round 14
// speedup vs baseline: 1.0616x; 1.0616x over previous
#include <cuda_runtime.h>
#include <cuda_fp16.h>
#include <mma.h>
#include <math.h>

using namespace nvcuda;

#define NN 8192
#define EE 262144
#define DIN 256
#define HID 64

// ---------------- scratch (device globals; no allocation allowed) ----------------
static __device__ __half g_S[(size_t)2 * NN * NN];         // 268 MB fp16 unnormalized exp scores
static __device__ float g_h1[NN * 128];
static __device__ float g_ht1[NN * 128];
static __device__ float g_h2[NN * 64];
static __device__ float g_htkg[NN * 64];
static __device__ float g_as1[NN * 2], g_ad1[NN * 2];
static __device__ float g_as2[NN], g_ad2[NN];
static __device__ float g_dinv[NN];
static __device__ float g_g1[NN * 64], g_he1[NN * 64];
static __device__ float g_g2[NN * 64], g_hekg[NN * 64];
static __device__ float g_q[NN * 64], g_k[NN * 64], g_v[NN * 64];
static __device__ __half g_qh[NN * 64], g_kh[NN * 64], g_vh[NN * 64];
static __device__ float g_attnout[NN * 64];
static __device__ float g_t1[NN * 64];
static __device__ float g_qn[NN * 2];
static __device__ float g_knm[2];
static __device__ float g_dsum[NN * 2];
static __device__ float g_bcomb[128 * 64];   // [fc1_W_top ; Wo@fc1_W_bot]
static __device__ float g_bfold[64];         // bo@fc1_W_bot + fc1_b
// CSR scratch (two graphs)
static __device__ int g_cnt_t[NN], g_cur_t[NN], g_off_t[NN + 1], g_srcs_t[EE];
static __device__ int g_cnt_e[NN], g_cur_e[NN], g_off_e[NN + 1], g_srcs_e[EE];

// ---------------- helpers ----------------
__device__ __forceinline__ void atomicMaxF(float* addr, float v) {
    if (v >= 0.f) atomicMax((int*)addr, __float_as_int(v));
    else          atomicMin((unsigned int*)addr, __float_as_uint(v));
}

__device__ __forceinline__ float leaky(float x) { return (x >= 0.f) ? x : 0.2f * x; }

// ---------------- fold Wo into fc1 (weights only; off critical path) ----------------
__global__ void fold_kernel(const float* __restrict__ Wo, const float* __restrict__ bo,
                            const float* __restrict__ fc1_W, const float* __restrict__ fc1_b,
                            float* __restrict__ Bcomb, float* __restrict__ bfold) {
    int i = blockIdx.x * blockDim.x + threadIdx.x;
    if (i < 4096) {
        Bcomb[i] = fc1_W[i];
    } else if (i < 8192) {
        int j = i - 4096;
        int r = j >> 6, c = j & 63;
        float s = 0.f;
#pragma unroll 8
        for (int k = 0; k < 64; k++) s = fmaf(Wo[r * 64 + k], fc1_W[(64 + k) * 64 + c], s);
        Bcomb[4096 + j] = s;
    } else if (i < 8256) {
        int c = i - 8192;
        float s = fc1_b[c];
#pragma unroll 8
        for (int k = 0; k < 64; k++) s = fmaf(bo[k], fc1_W[(64 + k) * 64 + c], s);
        bfold[c] = s;
    }
}

// ---------------- CSR build ----------------
__global__ void hist_kernel(const int* __restrict__ ei, int* cnt) {
    int e = blockIdx.x * blockDim.x + threadIdx.x;
    if (e < EE) atomicAdd(&cnt[ei[EE + e]], 1);
}

__global__ __launch_bounds__(1024) void scan_kernel(const int* __restrict__ cnt, int* __restrict__ off) {
    __shared__ int sm[1024];
    int tid = threadIdx.x;
    int base = tid * 8;
    int local[8];
    int s = 0;
#pragma unroll
    for (int j = 0; j < 8; j++) { local[j] = s; s += cnt[base + j]; }
    sm[tid] = s;
    __syncthreads();
    for (int d = 1; d < 1024; d <<= 1) {
        int v = (tid >= d) ? sm[tid - d] : 0;
        __syncthreads();
        sm[tid] += v;
        __syncthreads();
    }
    int pre = (tid == 0) ? 0 : sm[tid - 1];
#pragma unroll
    for (int j = 0; j < 8; j++) off[base + j] = pre + local[j];
    if (tid == 1023) off[NN] = sm[1023];
}

__global__ void scatter_kernel(const int* __restrict__ ei, const int* __restrict__ off,
                               int* cur, int* __restrict__ srcs) {
    int e = blockIdx.x * blockDim.x + threadIdx.x;
    if (e >= EE) return;
    int d = ei[EE + e];
    int p = off[d] + atomicAdd(&cur[d], 1);
    srcs[p] = ei[e];
}

__global__ void dinv_kernel(const int* __restrict__ cnt, float* dinv) {
    int i = blockIdx.x * blockDim.x + threadIdx.x;
    if (i < NN) dinv[i] = rsqrtf((float)(cnt[i] + 1));
}

// ---------------- generic tiled GEMM: C = act(A[M,K] @ B[K,N] + bias) ----------------
// A2 != null: logical A = [A | A2], each K/2 wide, row stride K/2 (fused concat).
// Ch != null: fp16 mirror of C.
// mode: 0 none; 1 GAT alpha (head = n0>>6); 2 qnorm; 3 knorm.
__global__ __launch_bounds__(256) void gemm64(const float* __restrict__ A,
                                              const float* __restrict__ A2,
                                              const float* __restrict__ B,
                                              const float* __restrict__ bias,
                                              float* __restrict__ C,
                                              __half* __restrict__ Ch,
                                              int M, int N, int K, int act,
                                              int mode,
                                              const float* __restrict__ att_s,
                                              const float* __restrict__ att_d,
                                              float* __restrict__ out1,
                                              float* __restrict__ out2,
                                              int H) {
    __shared__ float As[16][65];
    __shared__ float Bs[16][64];
    int tid = threadIdx.x;
    int tx = tid & 15, ty = tid >> 4;
    int m0 = blockIdx.y * 64, n0 = blockIdx.x * 64;
    float acc[4][4] = {};
    for (int k0 = 0; k0 < K; k0 += 16) {
        {
            int r = tid >> 2, c = (tid & 3) * 4;
            const float* src;
            if (A2 == nullptr) {
                src = A + (size_t)(m0 + r) * K + k0 + c;
            } else {
                int kk = k0 + c, half = K >> 1;
                src = (kk < half) ? (A  + (size_t)(m0 + r) * half + kk)
                                  : (A2 + (size_t)(m0 + r) * half + kk - half);
            }
            float4 av = *(const float4*)src;
            As[c + 0][r] = av.x; As[c + 1][r] = av.y; As[c + 2][r] = av.z; As[c + 3][r] = av.w;
        }
        {
            int r = tid >> 4, c = (tid & 15) * 4;
            float4 bv = *(const float4*)(B + (size_t)(k0 + r) * N + n0 + c);
            *(float4*)&Bs[r][c] = bv;
        }
        __syncthreads();
#pragma unroll
        for (int kk = 0; kk < 16; kk++) {
            float a[4], b[4];
#pragma unroll
            for (int i = 0; i < 4; i++) a[i] = As[kk][ty * 4 + i];
            float4 bv = *(float4*)&Bs[kk][tx * 4];
            b[0] = bv.x; b[1] = bv.y; b[2] = bv.z; b[3] = bv.w;
#pragma unroll
            for (int i = 0; i < 4; i++)
#pragma unroll
                for (int j = 0; j < 4; j++) acc[i][j] = fmaf(a[i], b[j], acc[i][j]);
        }
        __syncthreads();
    }
#pragma unroll
    for (int i = 0; i < 4; i++) {
        int m = m0 + ty * 4 + i;
        float v[4];
#pragma unroll
        for (int j = 0; j < 4; j++) {
            v[j] = acc[i][j];
            if (bias) v[j] += bias[n0 + tx * 4 + j];
        }
        if (mode == 1) {
            int head = n0 >> 6;
            float ss = 0.f, dd = 0.f;
#pragma unroll
            for (int j = 0; j < 4; j++) {
                int n = n0 + tx * 4 + j;
                ss = fmaf(v[j], att_s[n], ss);
                dd = fmaf(v[j], att_d[n], dd);
            }
#pragma unroll
            for (int o = 8; o > 0; o >>= 1) {
                ss += __shfl_down_sync(0xffffffffu, ss, o, 16);
                dd += __shfl_down_sync(0xffffffffu, dd, o, 16);
            }
            if (tx == 0) { out1[m * H + head] = ss; out2[m * H + head] = dd; }
        } else if (mode == 2 || mode == 3) {
            int head = tx >> 3;
            float sq = 0.f;
#pragma unroll
            for (int j = 0; j < 4; j++) sq = fmaf(v[j], v[j], sq);
#pragma unroll
            for (int o = 4; o > 0; o >>= 1) sq += __shfl_down_sync(0xffffffffu, sq, o, 8);
            if ((tx & 7) == 0) {
                if (mode == 2) out1[m * 2 + head] = sqrtf(sq);
                else           atomicMaxF(&out1[head], sqrtf(sq));
            }
        }
#pragma unroll
        for (int j = 0; j < 4; j++) {
            int n = n0 + tx * 4 + j;
            float w = v[j];
            if (act == 1) w = fmaxf(w, 0.f);
            else if (act == 2) w = (w > 0.f) ? w : expm1f(w);
            C[(size_t)m * N + n] = w;
            if (Ch) Ch[(size_t)m * N + n] = __float2half(w);
        }
    }
}

// ---------------- GAT: one warp per (dst, head), CSR gather, softmax in regs, bias+ELU ----------------
__global__ void gat_aggr_csr(const int* __restrict__ off, const int* __restrict__ srcs,
                             const float* __restrict__ as_, const float* __restrict__ ad_,
                             const float* __restrict__ hfeat, const float* __restrict__ bias,
                             float* __restrict__ out, int H) {
    int w = (blockIdx.x * blockDim.x + threadIdx.x) >> 5;
    int lane = threadIdx.x & 31;
    if (w >= NN * H) return;
    int d = w / H, hh = w - d * H;
    int beg = off[d], end = off[d + 1];
    float adv = ad_[w];
    float selfx = leaky(as_[w] + adv);
    float m = selfx;
    for (int i = beg + lane; i < end; i += 32)
        m = fmaxf(m, leaky(__ldg(&as_[srcs[i] * H + hh]) + adv));
#pragma unroll
    for (int o = 16; o > 0; o >>= 1) m = fmaxf(m, __shfl_xor_sync(0xffffffffu, m, o));
    float ssum = (lane == 0) ? __expf(selfx - m) : 0.f;
    for (int i = beg + lane; i < end; i += 32)
        ssum += __expf(leaky(__ldg(&as_[srcs[i] * H + hh]) + adv) - m);
#pragma unroll
    for (int o = 16; o > 0; o >>= 1) ssum += __shfl_xor_sync(0xffffffffu, ssum, o);
    float inv = 1.0f / (ssum + 1e-16f);
    int stride = H * HID;
    int fo = hh * HID;
    float alf = __expf(selfx - m) * inv;
    float a0 = alf * hfeat[(size_t)d * stride + fo + lane];
    float a1 = alf * hfeat[(size_t)d * stride + fo + lane + 32];
    int i = beg;
    for (; i + 1 < end; i += 2) {
        int s0 = srcs[i], s1 = srcs[i + 1];
        float x0 = leaky(__ldg(&as_[s0 * H + hh]) + adv);
        float x1 = leaky(__ldg(&as_[s1 * H + hh]) + adv);
        float al0 = __expf(x0 - m) * inv;
        float al1 = __expf(x1 - m) * inv;
        const float* h0 = hfeat + (size_t)s0 * stride + fo;
        const float* h1 = hfeat + (size_t)s1 * stride + fo;
        a0 = fmaf(al0, h0[lane], a0);
        a1 = fmaf(al0, h0[lane + 32], a1);
        a0 = fmaf(al1, h1[lane], a0);
        a1 = fmaf(al1, h1[lane + 32], a1);
    }
    if (i < end) {
        int s = srcs[i];
        float xx = leaky(__ldg(&as_[s * H + hh]) + adv);
        float al = __expf(xx - m) * inv;
        const float* hs = hfeat + (size_t)s * stride + fo;
        a0 = fmaf(al, hs[lane], a0);
        a1 = fmaf(al, hs[lane + 32], a1);
    }
    float v0 = a0 + bias[fo + lane];
    float v1 = a1 + bias[fo + lane + 32];
    v0 = (v0 > 0.f) ? v0 : expm1f(v0);   // ELU
    v1 = (v1 > 0.f) ? v1 : expm1f(v1);
    out[(size_t)d * stride + fo + lane] = v0;
    out[(size_t)d * stride + fo + lane + 32] = v1;
}

// ---------------- GCN: one warp per dst, CSR gather, fused bias+ReLU ----------------
__global__ void gcn_aggr_csr(const int* __restrict__ off, const int* __restrict__ srcs,
                             const float* __restrict__ hg, const float* __restrict__ dinv,
                             const float* __restrict__ bias, float* __restrict__ out) {
    int w = (blockIdx.x * blockDim.x + threadIdx.x) >> 5;
    int lane = threadIdx.x & 31;
    if (w >= NN) return;
    int d = w;
    int beg = off[d], end = off[d + 1];
    float dv = dinv[d];
    float a0 = dv * hg[(size_t)d * 64 + lane];
    float a1 = dv * hg[(size_t)d * 64 + lane + 32];
    int i = beg;
    for (; i + 1 < end; i += 2) {
        int s0 = srcs[i], s1 = srcs[i + 1];
        float ds0 = __ldg(&dinv[s0]);
        float ds1 = __ldg(&dinv[s1]);
        const float* h0 = hg + (size_t)s0 * 64;
        const float* h1 = hg + (size_t)s1 * 64;
        a0 = fmaf(ds0, h0[lane], a0);
        a1 = fmaf(ds0, h0[lane + 32], a1);
        a0 = fmaf(ds1, h1[lane], a0);
        a1 = fmaf(ds1, h1[lane + 32], a1);
    }
    if (i < end) {
        int s = srcs[i];
        float ds = __ldg(&dinv[s]);
        const float* hs = hg + (size_t)s * 64;
        a0 = fmaf(ds, hs[lane], a0);
        a1 = fmaf(ds, hs[lane + 32], a1);
    }
    float v0 = fmaf(dv, a0, bias[lane]);
    float v1 = fmaf(dv, a1, bias[lane + 32]);
    out[(size_t)d * 64 + lane] = fmaxf(v0, 0.f);
    out[(size_t)d * 64 + lane + 32] = fmaxf(v1, 0.f);
}

// ---------------- attention ----------------
// E[h][q][k] = exp(scale*(q.k - ||q||*knm)) via HMMA; fp16 store; fp32 row sums -> dsum.
__global__ __launch_bounds__(256) void qk_exp_wmma(const __half* __restrict__ Qh,
                                                   const __half* __restrict__ Kh,
                                                   const float* __restrict__ qn,
                                                   const float* __restrict__ knm,
                                                   __half* __restrict__ S,
                                                   float* __restrict__ dsum) {
    __shared__ __align__(32) char buf[36864];
    __half* Qs = (__half*)buf;                 // [64][40]
    __half* Ks = (__half*)(buf + 5120);        // [128][40]
    float* stage = (float*)buf;                // overlay after sync: [8][32*36]
    int h = blockIdx.z;
    int q0 = blockIdx.y * 64, k0 = blockIdx.x * 128;
    int tid = threadIdx.x, wid = tid >> 5, lane = tid & 31;
    {
        int r = tid >> 2, c8 = (tid & 3) * 8;
        *(uint4*)&Qs[r * 40 + c8] = *(const uint4*)(Qh + (size_t)(q0 + r) * 64 + h * 32 + c8);
    }
#pragma unroll
    for (int i = 0; i < 2; i++) {
        int idx = tid + i * 256;
        int r = idx >> 2, c8 = (idx & 3) * 8;
        *(uint4*)&Ks[r * 40 + c8] = *(const uint4*)(Kh + (size_t)(k0 + r) * 64 + h * 32 + c8);
    }
    __syncthreads();
    int qsub = (wid >> 2) * 32, ksub = (wid & 3) * 32;
    wmma::fragment<wmma::accumulator, 16, 16, 16, float> acc[2][2];
#pragma unroll
    for (int mi = 0; mi < 2; mi++)
#pragma unroll
        for (int ni = 0; ni < 2; ni++) wmma::fill_fragment(acc[mi][ni], 0.0f);
#pragma unroll
    for (int ks = 0; ks < 2; ks++) {
        wmma::fragment<wmma::matrix_a, 16, 16, 16, __half, wmma::row_major> a[2];
        wmma::fragment<wmma::matrix_b, 16, 16, 16, __half, wmma::col_major> b[2];
#pragma unroll
        for (int mi = 0; mi < 2; mi++)
            wmma::load_matrix_sync(a[mi], &Qs[(qsub + mi * 16) * 40 + ks * 16], 40);
#pragma unroll
        for (int ni = 0; ni < 2; ni++)
            wmma::load_matrix_sync(b[ni], &Ks[(ksub + ni * 16) * 40 + ks * 16], 40);
#pragma unroll
        for (int mi = 0; mi < 2; mi++)
#pragma unroll
            for (int ni = 0; ni < 2; ni++)
                wmma::mma_sync(acc[mi][ni], a[mi], b[ni], acc[mi][ni]);
    }
    __syncthreads();
    float* wst = stage + wid * (32 * 36);
#pragma unroll
    for (int mi = 0; mi < 2; mi++)
#pragma unroll
        for (int ni = 0; ni < 2; ni++)
            wmma::store_matrix_sync(&wst[mi * 16 * 36 + ni * 16], acc[mi][ni], 36, wmma::mem_row_major);
    const float sc = 0.17677669529663687f;   // 1/sqrt(32)
    int q = q0 + qsub + lane;
    float shiftsc = qn[q * 2 + h] * knm[h] * sc;
    const float* sp = &wst[lane * 36];
    float rs = 0.f;
    __half2 hv[16];
#pragma unroll
    for (int j = 0; j < 16; j++) {
        float e0 = __expf(fmaf(sp[2 * j], sc, -shiftsc));
        float e1 = __expf(fmaf(sp[2 * j + 1], sc, -shiftsc));
        hv[j] = __floats2half2_rn(e0, e1);
        rs += e0 + e1;
    }
    __half* Sp = S + (size_t)h * NN * NN + (size_t)q * NN + k0 + ksub;
#pragma unroll
    for (int t = 0; t < 4; t++) __stcs((uint4*)(Sp + t * 8), *(uint4*)&hv[t * 4]);
    atomicAdd(&dsum[q * 2 + h], rs);
}

// out[q, h*32+c] += sum_k (E/dsum)*V; streams head-averaged normalized weights.
// k-chunk 64; k-split 4 (round-12 geometry).
__global__ __launch_bounds__(256) void av_wmma(const __half* __restrict__ Sh,
                                               const __half* __restrict__ Vh,
                                               const float* __restrict__ dsum,
                                               float* __restrict__ out,
                                               float* __restrict__ avg) {
    __shared__ __align__(32) char buf[46080];
    __half* E0s = (__half*)buf;                // [128][72]
    __half* E1s = (__half*)(buf + 18432);      // [128][72]
    __half* Vs  = (__half*)(buf + 36864);      // [64][72]
    float* stage = (float*)buf;                // overlay at end: [8][32*36]
    __shared__ float invd[256];
    int q0 = blockIdx.x * 128;
    int kbase = blockIdx.y * 2048;
    int tid = threadIdx.x, wid = tid >> 5, lane = tid & 31;
    if (tid < 128) invd[tid] = 1.0f / dsum[(q0 + tid) * 2];
    else           invd[tid] = 1.0f / dsum[(q0 + tid - 128) * 2 + 1];
    int hh = wid >> 2, qsub = (wid & 3) * 32;
    wmma::fragment<wmma::accumulator, 16, 16, 16, float> acc[2][2];
#pragma unroll
    for (int mi = 0; mi < 2; mi++)
#pragma unroll
        for (int ni = 0; ni < 2; ni++) wmma::fill_fragment(acc[mi][ni], 0.0f);
    for (int kc = 0; kc < 2048; kc += 64) {
        __syncthreads();
#pragma unroll
        for (int i = 0; i < 4; i++) {
            int idx = tid + i * 256;
            int r = idx >> 3, c8 = (idx & 7) * 8;
            size_t goff = (size_t)(q0 + r) * NN + kbase + kc + c8;
            uint4 u0 = __ldcs((const uint4*)(Sh + goff));
            uint4 u1 = __ldcs((const uint4*)(Sh + (size_t)NN * NN + goff));
            *(uint4*)&E0s[r * 72 + c8] = u0;
            *(uint4*)&E1s[r * 72 + c8] = u1;
            float i0 = invd[r], i1 = invd[128 + r];
            __half2* a0 = (__half2*)&u0;
            __half2* a1 = (__half2*)&u1;
            float av8[8];
#pragma unroll
            for (int j = 0; j < 4; j++) {
                float2 f0 = __half22float2(a0[j]);
                float2 f1 = __half22float2(a1[j]);
                av8[2 * j]     = 0.5f * (f0.x * i0 + f1.x * i1);
                av8[2 * j + 1] = 0.5f * (f0.y * i0 + f1.y * i1);
            }
            __stcs((float4*)(avg + goff), *(float4*)&av8[0]);
            __stcs((float4*)(avg + goff + 4), *(float4*)&av8[4]);
        }
#pragma unroll
        for (int i = 0; i < 2; i++) {
            int idx = tid + i * 256;
            int r = idx >> 3, c8 = (idx & 7) * 8;
            *(uint4*)&Vs[r * 72 + c8] = *(const uint4*)(Vh + (size_t)(kbase + kc + r) * 64 + c8);
        }
        __syncthreads();
        __half* Es = hh ? E1s : E0s;
#pragma unroll
        for (int ks = 0; ks < 4; ks++) {
            wmma::fragment<wmma::matrix_a, 16, 16, 16, __half, wmma::row_major> a[2];
            wmma::fragment<wmma::matrix_b, 16, 16, 16, __half, wmma::row_major> b[2];
#pragma unroll
            for (int mi = 0; mi < 2; mi++)
                wmma::load_matrix_sync(a[mi], &Es[(qsub + mi * 16) * 72 + ks * 16], 72);
#pragma unroll
            for (int ni = 0; ni < 2; ni++)
                wmma::load_matrix_sync(b[ni], &Vs[(ks * 16) * 72 + hh * 32 + ni * 16], 72);
#pragma unroll
            for (int mi = 0; mi < 2; mi++)
#pragma unroll
                for (int ni = 0; ni < 2; ni++)
                    wmma::mma_sync(acc[mi][ni], a[mi], b[ni], acc[mi][ni]);
        }
    }
    __syncthreads();
    float* wst = stage + wid * (32 * 36);
#pragma unroll
    for (int mi = 0; mi < 2; mi++)
#pragma unroll
        for (int ni = 0; ni < 2; ni++)
            wmma::store_matrix_sync(&wst[mi * 16 * 36 + ni * 16], acc[mi][ni], 36, wmma::mem_row_major);
    int q = q0 + qsub + lane;
    float invq = invd[hh * 128 + qsub + lane];
    const float* sp = &wst[lane * 36];
#pragma unroll
    for (int j = 0; j < 32; j++)
        atomicAdd(&out[(size_t)q * 64 + hh * 32 + j], sp[j] * invq);
}

// ---------------- misc tail ----------------
__global__ void fc2_kernel(const float* __restrict__ t, const float* __restrict__ W,
                           const float* __restrict__ b, float* __restrict__ pred) {
    int w = (blockIdx.x * blockDim.x + threadIdx.x) >> 5;
    int lane = threadIdx.x & 31;
    if (w >= NN) return;
    float s = t[(size_t)w * 64 + lane] * W[lane] + t[(size_t)w * 64 + lane + 32] * W[lane + 32];
#pragma unroll
    for (int off = 16; off > 0; off >>= 1) s += __shfl_down_sync(0xffffffffu, s, off);
    if (lane == 0) pred[w] = s + b[0];
}

// ---------------- launch ----------------
extern "C" void kernel_launch(void* const* d_in, const int* in_sizes, int n_in,
                              void* d_out, int out_size) {
    const float* x       = (const float*)d_in[0];
    const int*   eit     = (const int*)d_in[1];
    const int*   eie     = (const int*)d_in[2];
    const float* gat1_W  = (const float*)d_in[3];
    const float* gat1_as = (const float*)d_in[4];
    const float* gat1_ad = (const float*)d_in[5];
    const float* gat1_b  = (const float*)d_in[6];
    const float* gat2_W  = (const float*)d_in[7];
    const float* gat2_as = (const float*)d_in[8];
    const float* gat2_ad = (const float*)d_in[9];
    const float* gat2_b  = (const float*)d_in[10];
    const float* gcn1_W  = (const float*)d_in[11];
    const float* gcn1_b  = (const float*)d_in[12];
    const float* gcn2_W  = (const float*)d_in[13];
    const float* gcn2_b  = (const float*)d_in[14];
    const float* Wq = (const float*)d_in[15]; const float* bq = (const float*)d_in[16];
    const float* Wk = (const float*)d_in[17]; const float* bk = (const float*)d_in[18];
    const float* Wv = (const float*)d_in[19]; const float* bv = (const float*)d_in[20];
    const float* Wo = (const float*)d_in[21]; const float* bo = (const float*)d_in[22];
    const float* fc1_W = (const float*)d_in[23]; const float* fc1_b = (const float*)d_in[24];
    const float* fc2_W = (const float*)d_in[25]; const float* fc2_b = (const float*)d_in[26];

    float* out_pred = (float*)d_out;
    float* out_attn = (float*)d_out + NN;

    __half *pS, *pqh, *pkh, *pvh;
    float *ph1, *pht1, *ph2, *phtkg, *pas1, *pad1, *pas2, *pad2;
    float *pdinv, *pg1, *phe1, *pg2, *phekg;
    float *pq, *pk, *pv, *pao, *pt1, *pqn, *pknm, *pdsum, *pbcomb, *pbfold;
    int *pcnt_t, *pcur_t, *poff_t, *psrcs_t, *pcnt_e, *pcur_e, *poff_e, *psrcs_e;
    cudaGetSymbolAddress((void**)&pS, g_S);
    cudaGetSymbolAddress((void**)&pqh, g_qh);    cudaGetSymbolAddress((void**)&pkh, g_kh);
    cudaGetSymbolAddress((void**)&pvh, g_vh);
    cudaGetSymbolAddress((void**)&ph1, g_h1);    cudaGetSymbolAddress((void**)&pht1, g_ht1);
    cudaGetSymbolAddress((void**)&ph2, g_h2);    cudaGetSymbolAddress((void**)&phtkg, g_htkg);
    cudaGetSymbolAddress((void**)&pas1, g_as1);  cudaGetSymbolAddress((void**)&pad1, g_ad1);
    cudaGetSymbolAddress((void**)&pas2, g_as2);  cudaGetSymbolAddress((void**)&pad2, g_ad2);
    cudaGetSymbolAddress((void**)&pdinv, g_dinv);
    cudaGetSymbolAddress((void**)&pg1, g_g1);    cudaGetSymbolAddress((void**)&phe1, g_he1);
    cudaGetSymbolAddress((void**)&pg2, g_g2);    cudaGetSymbolAddress((void**)&phekg, g_hekg);
    cudaGetSymbolAddress((void**)&pq, g_q);      cudaGetSymbolAddress((void**)&pk, g_k);
    cudaGetSymbolAddress((void**)&pv, g_v);      cudaGetSymbolAddress((void**)&pao, g_attnout);
    cudaGetSymbolAddress((void**)&pt1, g_t1);
    cudaGetSymbolAddress((void**)&pqn, g_qn);    cudaGetSymbolAddress((void**)&pknm, g_knm);
    cudaGetSymbolAddress((void**)&pdsum, g_dsum);
    cudaGetSymbolAddress((void**)&pbcomb, g_bcomb); cudaGetSymbolAddress((void**)&pbfold, g_bfold);
    cudaGetSymbolAddress((void**)&pcnt_t, g_cnt_t); cudaGetSymbolAddress((void**)&pcur_t, g_cur_t);
    cudaGetSymbolAddress((void**)&poff_t, g_off_t); cudaGetSymbolAddress((void**)&psrcs_t, g_srcs_t);
    cudaGetSymbolAddress((void**)&pcnt_e, g_cnt_e); cudaGetSymbolAddress((void**)&pcur_e, g_cur_e);
    cudaGetSymbolAddress((void**)&poff_e, g_off_e); cudaGetSymbolAddress((void**)&psrcs_e, g_srcs_e);

    static cudaStream_t s1 = nullptr, s2 = nullptr;
    static cudaEvent_t evRoot = nullptr, evT = nullptr, evB = nullptr;
    if (!s1) {
        cudaStreamCreateWithFlags(&s1, cudaStreamNonBlocking);
        cudaStreamCreateWithFlags(&s2, cudaStreamNonBlocking);
        cudaEventCreateWithFlags(&evRoot, cudaEventDisableTiming);
        cudaEventCreateWithFlags(&evT, cudaEventDisableTiming);
        cudaEventCreateWithFlags(&evB, cudaEventDisableTiming);
    }

    const int T = 256;
    const int EB = (EE + T - 1) / T;

    // ===== fork =====
    cudaEventRecord(evRoot, 0);
    cudaStreamWaitEvent(s1, evRoot, 0);
    cudaStreamWaitEvent(s2, evRoot, 0);

    // ----- s1: CSR for TKG graph -----
    cudaMemsetAsync(pcnt_t, 0, NN * sizeof(int), s1);
    cudaMemsetAsync(pcur_t, 0, NN * sizeof(int), s1);
    hist_kernel<<<EB, T, 0, s1>>>(eit, pcnt_t);
    scan_kernel<<<1, 1024, 0, s1>>>(pcnt_t, poff_t);
    scatter_kernel<<<EB, T, 0, s1>>>(eit, poff_t, pcur_t, psrcs_t);
    cudaEventRecord(evT, s1);

    // ----- s2: fold(Wo->fc1) + CSR EKG + GCN branch + K/V projections (+k-norms) -----
    fold_kernel<<<33, T, 0, s2>>>(Wo, bo, fc1_W, fc1_b, pbcomb, pbfold);
    cudaMemsetAsync(pcnt_e, 0, NN * sizeof(int), s2);
    cudaMemsetAsync(pcur_e, 0, NN * sizeof(int), s2);
    cudaMemsetAsync(pknm, 0, 2 * sizeof(float), s2);
    hist_kernel<<<EB, T, 0, s2>>>(eie, pcnt_e);
    scan_kernel<<<1, 1024, 0, s2>>>(pcnt_e, poff_e);
    scatter_kernel<<<EB, T, 0, s2>>>(eie, poff_e, pcur_e, psrcs_e);
    dinv_kernel<<<(NN + T - 1) / T, T, 0, s2>>>(pcnt_e, pdinv);
    gemm64<<<dim3(1, 128), 256, 0, s2>>>(x, nullptr, gcn1_W, nullptr, pg1, nullptr, NN, 64, DIN, 0,
                                         0, nullptr, nullptr, nullptr, nullptr, 0);
    gcn_aggr_csr<<<(NN * 32 + T - 1) / T, T, 0, s2>>>(poff_e, psrcs_e, pg1, pdinv, gcn1_b, phe1);
    gemm64<<<dim3(1, 128), 256, 0, s2>>>(phe1, nullptr, gcn2_W, nullptr, pg2, nullptr, NN, 64, 64, 0,
                                         0, nullptr, nullptr, nullptr, nullptr, 0);
    gcn_aggr_csr<<<(NN * 32 + T - 1) / T, T, 0, s2>>>(poff_e, psrcs_e, pg2, pdinv, gcn2_b, phekg);
    gemm64<<<dim3(1, 128), 256, 0, s2>>>(phekg, nullptr, Wk, bk, pk, pkh, NN, 64, 64, 0,
                                         3, nullptr, nullptr, pknm, nullptr, 0);
    gemm64<<<dim3(1, 128), 256, 0, s2>>>(phekg, nullptr, Wv, bv, pv, pvh, NN, 64, 64, 0,
                                         0, nullptr, nullptr, nullptr, nullptr, 0);
    cudaEventRecord(evB, s2);

    // ----- s0: GAT branch (critical path) -----
    gemm64<<<dim3(2, 128), 256>>>(x, nullptr, gat1_W, nullptr, ph1, nullptr, NN, 128, DIN, 0,
                                  1, gat1_as, gat1_ad, pas1, pad1, 2);
    cudaStreamWaitEvent(0, evT, 0);
    gat_aggr_csr<<<(NN * 2 * 32 + T - 1) / T, T>>>(poff_t, psrcs_t, pas1, pad1, ph1, gat1_b, pht1, 2);
    gemm64<<<dim3(1, 128), 256>>>(pht1, nullptr, gat2_W, nullptr, ph2, nullptr, NN, 64, 128, 0,
                                  1, gat2_as, gat2_ad, pas2, pad2, 1);
    gat_aggr_csr<<<(NN * 32 + T - 1) / T, T>>>(poff_t, psrcs_t, pas2, pad2, ph2, gat2_b, phtkg, 1);
    gemm64<<<dim3(1, 128), 256>>>(phtkg, nullptr, Wq, bq, pq, pqh, NN, 64, 64, 0,
                                  2, nullptr, nullptr, pqn, nullptr, 0);
    cudaMemsetAsync(pdsum, 0, NN * 2 * sizeof(float));
    cudaMemsetAsync(pao, 0, (size_t)NN * 64 * sizeof(float));
    cudaStreamWaitEvent(0, evB, 0);
    qk_exp_wmma<<<dim3(64, 128, 2), 256>>>(pqh, pkh, pqn, pknm, pS, pdsum);
    av_wmma<<<dim3(64, 4), 256>>>(pS, pvh, pdsum, pao, out_attn);
    gemm64<<<dim3(1, 128), 256>>>(phtkg, pao, pbcomb, pbfold, pt1, nullptr, NN, 64, 128, 1,
                                  0, nullptr, nullptr, nullptr, nullptr, 0);
    fc2_kernel<<<(NN * 32 + T - 1) / T, T>>>(pt1, fc2_W, fc2_b, out_pred);
}

// round 15
// speedup vs baseline: 1.0619x; 1.0003x over previous
#include <cuda_runtime.h>
#include <cuda_fp16.h>
#include <mma.h>
#include <math.h>

using namespace nvcuda;

#define NN 8192
#define EE 262144
#define DIN 256
#define HID 64

// ---------------- scratch (device globals; no allocation allowed) ----------------
static __device__ __half g_S[(size_t)2 * NN * NN];         // 268 MB fp16 unnormalized exp scores
static __device__ float g_h1[NN * 128];
static __device__ float g_ht1[NN * 128];
static __device__ float g_h2[NN * 64];
static __device__ float g_htkg[NN * 64];
static __device__ float g_as1[NN * 2], g_ad1[NN * 2];
static __device__ float g_as2[NN], g_ad2[NN];
static __device__ float g_dinv[NN];
static __device__ float g_g1[NN * 64], g_he1[NN * 64];
static __device__ float g_g2[NN * 64], g_hekg[NN * 64];
static __device__ float g_q[NN * 64], g_k[NN * 64], g_v[NN * 64];
static __device__ __half g_qh[NN * 64], g_kh[NN * 64], g_vh[NN * 64];
static __device__ float g_attnout[NN * 64];
static __device__ float g_qn[NN * 2];
static __device__ float g_knm[2];
static __device__ float g_dsum[NN * 2];
static __device__ float g_bcomb[128 * 64];   // [fc1_W_top ; Wo@fc1_W_bot]
static __device__ float g_bfold[64];         // bo@fc1_W_bot + fc1_b
// CSR scratch (two graphs)
static __device__ int g_cnt_t[NN], g_cur_t[NN], g_off_t[NN + 1], g_srcs_t[EE];
static __device__ int g_cnt_e[NN], g_cur_e[NN], g_off_e[NN + 1], g_srcs_e[EE];

// ---------------- helpers ----------------
__device__ __forceinline__ void atomicMaxF(float* addr, float v) {
    if (v >= 0.f) atomicMax((int*)addr, __float_as_int(v));
    else          atomicMin((unsigned int*)addr, __float_as_uint(v));
}

__device__ __forceinline__ float leaky(float x) { return (x >= 0.f) ? x : 0.2f * x; }

// ---------------- fold Wo into fc1 (weights only; off critical path) ----------------
__global__ void fold_kernel(const float* __restrict__ Wo, const float* __restrict__ bo,
                            const float* __restrict__ fc1_W, const float* __restrict__ fc1_b,
                            float* __restrict__ Bcomb, float* __restrict__ bfold) {
    int i = blockIdx.x * blockDim.x + threadIdx.x;
    if (i < 4096) {
        Bcomb[i] = fc1_W[i];
    } else if (i < 8192) {
        int j = i - 4096;
        int r = j >> 6, c = j & 63;
        float s = 0.f;
#pragma unroll 8
        for (int k = 0; k < 64; k++) s = fmaf(Wo[r * 64 + k], fc1_W[(64 + k) * 64 + c], s);
        Bcomb[4096 + j] = s;
    } else if (i < 8256) {
        int c = i - 8192;
        float s = fc1_b[c];
#pragma unroll 8
        for (int k = 0; k < 64; k++) s = fmaf(bo[k], fc1_W[(64 + k) * 64 + c], s);
        bfold[c] = s;
    }
}

// ---------------- CSR build ----------------
__global__ void hist_kernel(const int* __restrict__ ei, int* cnt) {
    int e = blockIdx.x * blockDim.x + threadIdx.x;
    if (e < EE) atomicAdd(&cnt[ei[EE + e]], 1);
}

__global__ __launch_bounds__(1024) void scan_kernel(const int* __restrict__ cnt, int* __restrict__ off) {
    __shared__ int sm[1024];
    int tid = threadIdx.x;
    int base = tid * 8;
    int local[8];
    int s = 0;
#pragma unroll
    for (int j = 0; j < 8; j++) { local[j] = s; s += cnt[base + j]; }
    sm[tid] = s;
    __syncthreads();
    for (int d = 1; d < 1024; d <<= 1) {
        int v = (tid >= d) ? sm[tid - d] : 0;
        __syncthreads();
        sm[tid] += v;
        __syncthreads();
    }
    int pre = (tid == 0) ? 0 : sm[tid - 1];
#pragma unroll
    for (int j = 0; j < 8; j++) off[base + j] = pre + local[j];
    if (tid == 1023) off[NN] = sm[1023];
}

__global__ void scatter_kernel(const int* __restrict__ ei, const int* __restrict__ off,
                               int* cur, int* __restrict__ srcs) {
    int e = blockIdx.x * blockDim.x + threadIdx.x;
    if (e >= EE) return;
    int d = ei[EE + e];
    int p = off[d] + atomicAdd(&cur[d], 1);
    srcs[p] = ei[e];
}

__global__ void dinv_kernel(const int* __restrict__ cnt, float* dinv) {
    int i = blockIdx.x * blockDim.x + threadIdx.x;
    if (i < NN) dinv[i] = rsqrtf((float)(cnt[i] + 1));
}

// ---------------- generic tiled GEMM: C = act(A[M,K] @ B[K,N] + bias) ----------------
// A2 != null: logical A = [A | A2], each K/2 wide, row stride K/2 (fused concat).
// Ch != null: fp16 mirror of C. C may be null (epilogue-only output, mode 4).
// mode: 0 none; 1 GAT alpha (head = n0>>6); 2 qnorm; 3 knorm;
//       4 fc2 fuse: out1[m] = (act(row) . att_s) + att_d[0]   (N==64)
__global__ __launch_bounds__(256) void gemm64(const float* __restrict__ A,
                                              const float* __restrict__ A2,
                                              const float* __restrict__ B,
                                              const float* __restrict__ bias,
                                              float* __restrict__ C,
                                              __half* __restrict__ Ch,
                                              int M, int N, int K, int act,
                                              int mode,
                                              const float* __restrict__ att_s,
                                              const float* __restrict__ att_d,
                                              float* __restrict__ out1,
                                              float* __restrict__ out2,
                                              int H) {
    __shared__ float As[16][65];
    __shared__ float Bs[16][64];
    int tid = threadIdx.x;
    int tx = tid & 15, ty = tid >> 4;
    int m0 = blockIdx.y * 64, n0 = blockIdx.x * 64;
    float acc[4][4] = {};
    for (int k0 = 0; k0 < K; k0 += 16) {
        {
            int r = tid >> 2, c = (tid & 3) * 4;
            const float* src;
            if (A2 == nullptr) {
                src = A + (size_t)(m0 + r) * K + k0 + c;
            } else {
                int kk = k0 + c, half = K >> 1;
                src = (kk < half) ? (A  + (size_t)(m0 + r) * half + kk)
                                  : (A2 + (size_t)(m0 + r) * half + kk - half);
            }
            float4 av = *(const float4*)src;
            As[c + 0][r] = av.x; As[c + 1][r] = av.y; As[c + 2][r] = av.z; As[c + 3][r] = av.w;
        }
        {
            int r = tid >> 4, c = (tid & 15) * 4;
            float4 bv = *(const float4*)(B + (size_t)(k0 + r) * N + n0 + c);
            *(float4*)&Bs[r][c] = bv;
        }
        __syncthreads();
#pragma unroll
        for (int kk = 0; kk < 16; kk++) {
            float a[4], b[4];
#pragma unroll
            for (int i = 0; i < 4; i++) a[i] = As[kk][ty * 4 + i];
            float4 bv = *(float4*)&Bs[kk][tx * 4];
            b[0] = bv.x; b[1] = bv.y; b[2] = bv.z; b[3] = bv.w;
#pragma unroll
            for (int i = 0; i < 4; i++)
#pragma unroll
                for (int j = 0; j < 4; j++) acc[i][j] = fmaf(a[i], b[j], acc[i][j]);
        }
        __syncthreads();
    }
#pragma unroll
    for (int i = 0; i < 4; i++) {
        int m = m0 + ty * 4 + i;
        float v[4];
#pragma unroll
        for (int j = 0; j < 4; j++) {
            v[j] = acc[i][j];
            if (bias) v[j] += bias[n0 + tx * 4 + j];
        }
        if (mode == 1) {
            int head = n0 >> 6;
            float ss = 0.f, dd = 0.f;
#pragma unroll
            for (int j = 0; j < 4; j++) {
                int n = n0 + tx * 4 + j;
                ss = fmaf(v[j], att_s[n], ss);
                dd = fmaf(v[j], att_d[n], dd);
            }
#pragma unroll
            for (int o = 8; o > 0; o >>= 1) {
                ss += __shfl_down_sync(0xffffffffu, ss, o, 16);
                dd += __shfl_down_sync(0xffffffffu, dd, o, 16);
            }
            if (tx == 0) { out1[m * H + head] = ss; out2[m * H + head] = dd; }
        } else if (mode == 2 || mode == 3) {
            int head = tx >> 3;
            float sq = 0.f;
#pragma unroll
            for (int j = 0; j < 4; j++) sq = fmaf(v[j], v[j], sq);
#pragma unroll
            for (int o = 4; o > 0; o >>= 1) sq += __shfl_down_sync(0xffffffffu, sq, o, 8);
            if ((tx & 7) == 0) {
                if (mode == 2) out1[m * 2 + head] = sqrtf(sq);
                else           atomicMaxF(&out1[head], sqrtf(sq));
            }
        }
        float wv[4];
#pragma unroll
        for (int j = 0; j < 4; j++) {
            float w = v[j];
            if (act == 1) w = fmaxf(w, 0.f);
            else if (act == 2) w = (w > 0.f) ? w : expm1f(w);
            wv[j] = w;
        }
        if (mode == 4) {
            float ss = 0.f;
#pragma unroll
            for (int j = 0; j < 4; j++) ss = fmaf(wv[j], att_s[n0 + tx * 4 + j], ss);
#pragma unroll
            for (int o = 8; o > 0; o >>= 1) ss += __shfl_down_sync(0xffffffffu, ss, o, 16);
            if (tx == 0) out1[m] = ss + att_d[0];
        }
        if (C) {
#pragma unroll
            for (int j = 0; j < 4; j++) {
                int n = n0 + tx * 4 + j;
                C[(size_t)m * N + n] = wv[j];
                if (Ch) Ch[(size_t)m * N + n] = __float2half(wv[j]);
            }
        } else if (Ch) {
#pragma unroll
            for (int j = 0; j < 4; j++)
                Ch[(size_t)m * N + n0 + tx * 4 + j] = __float2half(wv[j]);
        }
    }
}

// ---------------- GAT: one warp per (dst, head), CSR gather, softmax in regs, bias+ELU ----------------
__global__ void gat_aggr_csr(const int* __restrict__ off, const int* __restrict__ srcs,
                             const float* __restrict__ as_, const float* __restrict__ ad_,
                             const float* __restrict__ hfeat, const float* __restrict__ bias,
                             float* __restrict__ out, int H) {
    int w = (blockIdx.x * blockDim.x + threadIdx.x) >> 5;
    int lane = threadIdx.x & 31;
    if (w >= NN * H) return;
    int d = w / H, hh = w - d * H;
    int beg = off[d], end = off[d + 1];
    float adv = ad_[w];
    float selfx = leaky(as_[w] + adv);
    float m = selfx;
    for (int i = beg + lane; i < end; i += 32)
        m = fmaxf(m, leaky(__ldg(&as_[srcs[i] * H + hh]) + adv));
#pragma unroll
    for (int o = 16; o > 0; o >>= 1) m = fmaxf(m, __shfl_xor_sync(0xffffffffu, m, o));
    float ssum = (lane == 0) ? __expf(selfx - m) : 0.f;
    for (int i = beg + lane; i < end; i += 32)
        ssum += __expf(leaky(__ldg(&as_[srcs[i] * H + hh]) + adv) - m);
#pragma unroll
    for (int o = 16; o > 0; o >>= 1) ssum += __shfl_xor_sync(0xffffffffu, ssum, o);
    float inv = 1.0f / (ssum + 1e-16f);
    int stride = H * HID;
    int fo = hh * HID;
    float alf = __expf(selfx - m) * inv;
    float a0 = alf * hfeat[(size_t)d * stride + fo + lane];
    float a1 = alf * hfeat[(size_t)d * stride + fo + lane + 32];
    int i = beg;
    for (; i + 1 < end; i += 2) {
        int s0 = srcs[i], s1 = srcs[i + 1];
        float x0 = leaky(__ldg(&as_[s0 * H + hh]) + adv);
        float x1 = leaky(__ldg(&as_[s1 * H + hh]) + adv);
        float al0 = __expf(x0 - m) * inv;
        float al1 = __expf(x1 - m) * inv;
        const float* h0 = hfeat + (size_t)s0 * stride + fo;
        const float* h1 = hfeat + (size_t)s1 * stride + fo;
        a0 = fmaf(al0, h0[lane], a0);
        a1 = fmaf(al0, h0[lane + 32], a1);
        a0 = fmaf(al1, h1[lane], a0);
        a1 = fmaf(al1, h1[lane + 32], a1);
    }
    if (i < end) {
        int s = srcs[i];
        float xx = leaky(__ldg(&as_[s * H + hh]) + adv);
        float al = __expf(xx - m) * inv;
        const float* hs = hfeat + (size_t)s * stride + fo;
        a0 = fmaf(al, hs[lane], a0);
        a1 = fmaf(al, hs[lane + 32], a1);
    }
    float v0 = a0 + bias[fo + lane];
    float v1 = a1 + bias[fo + lane + 32];
    v0 = (v0 > 0.f) ? v0 : expm1f(v0);   // ELU
    v1 = (v1 > 0.f) ? v1 : expm1f(v1);
    out[(size_t)d * stride + fo + lane] = v0;
    out[(size_t)d * stride + fo + lane + 32] = v1;
}

// ---------------- GCN: one warp per dst, CSR gather, fused bias+ReLU ----------------
__global__ void gcn_aggr_csr(const int* __restrict__ off, const int* __restrict__ srcs,
                             const float* __restrict__ hg, const float* __restrict__ dinv,
                             const float* __restrict__ bias, float* __restrict__ out) {
    int w = (blockIdx.x * blockDim.x + threadIdx.x) >> 5;
    int lane = threadIdx.x & 31;
    if (w >= NN) return;
    int d = w;
    int beg = off[d], end = off[d + 1];
    float dv = dinv[d];
    float a0 = dv * hg[(size_t)d * 64 + lane];
    float a1 = dv * hg[(size_t)d * 64 + lane + 32];
    int i = beg;
    for (; i + 1 < end; i += 2) {
        int s0 = srcs[i], s1 = srcs[i + 1];
        float ds0 = __ldg(&dinv[s0]);
        float ds1 = __ldg(&dinv[s1]);
        const float* h0 = hg + (size_t)s0 * 64;
        const float* h1 = hg + (size_t)s1 * 64;
        a0 = fmaf(ds0, h0[lane], a0);
        a1 = fmaf(ds0, h0[lane + 32], a1);
        a0 = fmaf(ds1, h1[lane], a0);
        a1 = fmaf(ds1, h1[lane + 32], a1);
    }
    if (i < end) {
        int s = srcs[i];
        float ds = __ldg(&dinv[s]);
        const float* hs = hg + (size_t)s * 64;
        a0 = fmaf(ds, hs[lane], a0);
        a1 = fmaf(ds, hs[lane + 32], a1);
    }
    float v0 = fmaf(dv, a0, bias[lane]);
    float v1 = fmaf(dv, a1, bias[lane + 32]);
    out[(size_t)d * 64 + lane] = fmaxf(v0, 0.f);
    out[(size_t)d * 64 + lane + 32] = fmaxf(v1, 0.f);
}

// ---------------- attention ----------------
// E[h][q][k] = exp(scale*(q.k - ||q||*knm)) via HMMA; fp16 store; fp32 row sums -> dsum.
// qoff: q-range offset (pipelined halves).
__global__ __launch_bounds__(256) void qk_exp_wmma(const __half* __restrict__ Qh,
                                                   const __half* __restrict__ Kh,
                                                   const float* __restrict__ qn,
                                                   const float* __restrict__ knm,
                                                   __half* __restrict__ S,
                                                   float* __restrict__ dsum,
                                                   int qoff) {
    __shared__ __align__(32) char buf[36864];
    __half* Qs = (__half*)buf;                 // [64][40]
    __half* Ks = (__half*)(buf + 5120);        // [128][40]
    float* stage = (float*)buf;                // overlay after sync: [8][32*36]
    int h = blockIdx.z;
    int q0 = qoff + blockIdx.y * 64, k0 = blockIdx.x * 128;
    int tid = threadIdx.x, wid = tid >> 5, lane = tid & 31;
    {
        int r = tid >> 2, c8 = (tid & 3) * 8;
        *(uint4*)&Qs[r * 40 + c8] = *(const uint4*)(Qh + (size_t)(q0 + r) * 64 + h * 32 + c8);
    }
#pragma unroll
    for (int i = 0; i < 2; i++) {
        int idx = tid + i * 256;
        int r = idx >> 2, c8 = (idx & 3) * 8;
        *(uint4*)&Ks[r * 40 + c8] = *(const uint4*)(Kh + (size_t)(k0 + r) * 64 + h * 32 + c8);
    }
    __syncthreads();
    int qsub = (wid >> 2) * 32, ksub = (wid & 3) * 32;
    wmma::fragment<wmma::accumulator, 16, 16, 16, float> acc[2][2];
#pragma unroll
    for (int mi = 0; mi < 2; mi++)
#pragma unroll
        for (int ni = 0; ni < 2; ni++) wmma::fill_fragment(acc[mi][ni], 0.0f);
#pragma unroll
    for (int ks = 0; ks < 2; ks++) {
        wmma::fragment<wmma::matrix_a, 16, 16, 16, __half, wmma::row_major> a[2];
        wmma::fragment<wmma::matrix_b, 16, 16, 16, __half, wmma::col_major> b[2];
#pragma unroll
        for (int mi = 0; mi < 2; mi++)
            wmma::load_matrix_sync(a[mi], &Qs[(qsub + mi * 16) * 40 + ks * 16], 40);
#pragma unroll
        for (int ni = 0; ni < 2; ni++)
            wmma::load_matrix_sync(b[ni], &Ks[(ksub + ni * 16) * 40 + ks * 16], 40);
#pragma unroll
        for (int mi = 0; mi < 2; mi++)
#pragma unroll
            for (int ni = 0; ni < 2; ni++)
                wmma::mma_sync(acc[mi][ni], a[mi], b[ni], acc[mi][ni]);
    }
    __syncthreads();
    float* wst = stage + wid * (32 * 36);
#pragma unroll
    for (int mi = 0; mi < 2; mi++)
#pragma unroll
        for (int ni = 0; ni < 2; ni++)
            wmma::store_matrix_sync(&wst[mi * 16 * 36 + ni * 16], acc[mi][ni], 36, wmma::mem_row_major);
    const float sc = 0.17677669529663687f;   // 1/sqrt(32)
    int q = q0 + qsub + lane;
    float shiftsc = qn[q * 2 + h] * knm[h] * sc;
    const float* sp = &wst[lane * 36];
    float rs = 0.f;
    __half2 hv[16];
#pragma unroll
    for (int j = 0; j < 16; j++) {
        float e0 = __expf(fmaf(sp[2 * j], sc, -shiftsc));
        float e1 = __expf(fmaf(sp[2 * j + 1], sc, -shiftsc));
        hv[j] = __floats2half2_rn(e0, e1);
        rs += e0 + e1;
    }
    __half* Sp = S + (size_t)h * NN * NN + (size_t)q * NN + k0 + ksub;
#pragma unroll
    for (int t = 0; t < 4; t++) __stcs((uint4*)(Sp + t * 8), *(uint4*)&hv[t * 4]);
    atomicAdd(&dsum[q * 2 + h], rs);
}

// out[q, h*32+c] += sum_k (E/dsum)*V; streams head-averaged normalized weights.
// k-chunk 64; k-split 4; qoff for pipelined halves.
__global__ __launch_bounds__(256) void av_wmma(const __half* __restrict__ Sh,
                                               const __half* __restrict__ Vh,
                                               const float* __restrict__ dsum,
                                               float* __restrict__ out,
                                               float* __restrict__ avg,
                                               int qoff) {
    __shared__ __align__(32) char buf[46080];
    __half* E0s = (__half*)buf;                // [128][72]
    __half* E1s = (__half*)(buf + 18432);      // [128][72]
    __half* Vs  = (__half*)(buf + 36864);      // [64][72]
    float* stage = (float*)buf;                // overlay at end: [8][32*36]
    __shared__ float invd[256];
    int q0 = qoff + blockIdx.x * 128;
    int kbase = blockIdx.y * 2048;
    int tid = threadIdx.x, wid = tid >> 5, lane = tid & 31;
    if (tid < 128) invd[tid] = 1.0f / dsum[(q0 + tid) * 2];
    else           invd[tid] = 1.0f / dsum[(q0 + tid - 128) * 2 + 1];
    int hh = wid >> 2, qsub = (wid & 3) * 32;
    wmma::fragment<wmma::accumulator, 16, 16, 16, float> acc[2][2];
#pragma unroll
    for (int mi = 0; mi < 2; mi++)
#pragma unroll
        for (int ni = 0; ni < 2; ni++) wmma::fill_fragment(acc[mi][ni], 0.0f);
    for (int kc = 0; kc < 2048; kc += 64) {
        __syncthreads();
#pragma unroll
        for (int i = 0; i < 4; i++) {
            int idx = tid + i * 256;
            int r = idx >> 3, c8 = (idx & 7) * 8;
            size_t goff = (size_t)(q0 + r) * NN + kbase + kc + c8;
            uint4 u0 = __ldcs((const uint4*)(Sh + goff));
            uint4 u1 = __ldcs((const uint4*)(Sh + (size_t)NN * NN + goff));
            *(uint4*)&E0s[r * 72 + c8] = u0;
            *(uint4*)&E1s[r * 72 + c8] = u1;
            float i0 = invd[r], i1 = invd[128 + r];
            __half2* a0 = (__half2*)&u0;
            __half2* a1 = (__half2*)&u1;
            float av8[8];
#pragma unroll
            for (int j = 0; j < 4; j++) {
                float2 f0 = __half22float2(a0[j]);
                float2 f1 = __half22float2(a1[j]);
                av8[2 * j]     = 0.5f * (f0.x * i0 + f1.x * i1);
                av8[2 * j + 1] = 0.5f * (f0.y * i0 + f1.y * i1);
            }
            __stcs((float4*)(avg + goff), *(float4*)&av8[0]);
            __stcs((float4*)(avg + goff + 4), *(float4*)&av8[4]);
        }
#pragma unroll
        for (int i = 0; i < 2; i++) {
            int idx = tid + i * 256;
            int r = idx >> 3, c8 = (idx & 7) * 8;
            *(uint4*)&Vs[r * 72 + c8] = *(const uint4*)(Vh + (size_t)(kbase + kc + r) * 64 + c8);
        }
        __syncthreads();
        __half* Es = hh ? E1s : E0s;
#pragma unroll
        for (int ks = 0; ks < 4; ks++) {
            wmma::fragment<wmma::matrix_a, 16, 16, 16, __half, wmma::row_major> a[2];
            wmma::fragment<wmma::matrix_b, 16, 16, 16, __half, wmma::row_major> b[2];
#pragma unroll
            for (int mi = 0; mi < 2; mi++)
                wmma::load_matrix_sync(a[mi], &Es[(qsub + mi * 16) * 72 + ks * 16], 72);
#pragma unroll
            for (int ni = 0; ni < 2; ni++)
                wmma::load_matrix_sync(b[ni], &Vs[(ks * 16) * 72 + hh * 32 + ni * 16], 72);
#pragma unroll
            for (int mi = 0; mi < 2; mi++)
#pragma unroll
                for (int ni = 0; ni < 2; ni++)
                    wmma::mma_sync(acc[mi][ni], a[mi], b[ni], acc[mi][ni]);
        }
    }
    __syncthreads();
    float* wst = stage + wid * (32 * 36);
#pragma unroll
    for (int mi = 0; mi < 2; mi++)
#pragma unroll
        for (int ni = 0; ni < 2; ni++)
            wmma::store_matrix_sync(&wst[mi * 16 * 36 + ni * 16], acc[mi][ni], 36, wmma::mem_row_major);
    int q = q0 + qsub + lane;
    float invq = invd[hh * 128 + qsub + lane];
    const float* sp = &wst[lane * 36];
#pragma unroll
    for (int j = 0; j < 32; j++)
        atomicAdd(&out[(size_t)q * 64 + hh * 32 + j], sp[j] * invq);
}

// ---------------- launch ----------------
extern "C" void kernel_launch(void* const* d_in, const int* in_sizes, int n_in,
                              void* d_out, int out_size) {
    const float* x       = (const float*)d_in[0];
    const int*   eit     = (const int*)d_in[1];
    const int*   eie     = (const int*)d_in[2];
    const float* gat1_W  = (const float*)d_in[3];
    const float* gat1_as = (const float*)d_in[4];
    const float* gat1_ad = (const float*)d_in[5];
    const float* gat1_b  = (const float*)d_in[6];
    const float* gat2_W  = (const float*)d_in[7];
    const float* gat2_as = (const float*)d_in[8];
    const float* gat2_ad = (const float*)d_in[9];
    const float* gat2_b  = (const float*)d_in[10];
    const float* gcn1_W  = (const float*)d_in[11];
    const float* gcn1_b  = (const float*)d_in[12];
    const float* gcn2_W  = (const float*)d_in[13];
    const float* gcn2_b  = (const float*)d_in[14];
    const float* Wq = (const float*)d_in[15]; const float* bq = (const float*)d_in[16];
    const float* Wk = (const float*)d_in[17]; const float* bk = (const float*)d_in[18];
    const float* Wv = (const float*)d_in[19]; const float* bv = (const float*)d_in[20];
    const float* Wo = (const float*)d_in[21]; const float* bo = (const float*)d_in[22];
    const float* fc1_W = (const float*)d_in[23]; const float* fc1_b = (const float*)d_in[24];
    const float* fc2_W = (const float*)d_in[25]; const float* fc2_b = (const float*)d_in[26];

    float* out_pred = (float*)d_out;
    float* out_attn = (float*)d_out + NN;

    __half *pS, *pqh, *pkh, *pvh;
    float *ph1, *pht1, *ph2, *phtkg, *pas1, *pad1, *pas2, *pad2;
    float *pdinv, *pg1, *phe1, *pg2, *phekg;
    float *pq, *pk, *pv, *pao, *pqn, *pknm, *pdsum, *pbcomb, *pbfold;
    int *pcnt_t, *pcur_t, *poff_t, *psrcs_t, *pcnt_e, *pcur_e, *poff_e, *psrcs_e;
    cudaGetSymbolAddress((void**)&pS, g_S);
    cudaGetSymbolAddress((void**)&pqh, g_qh);    cudaGetSymbolAddress((void**)&pkh, g_kh);
    cudaGetSymbolAddress((void**)&pvh, g_vh);
    cudaGetSymbolAddress((void**)&ph1, g_h1);    cudaGetSymbolAddress((void**)&pht1, g_ht1);
    cudaGetSymbolAddress((void**)&ph2, g_h2);    cudaGetSymbolAddress((void**)&phtkg, g_htkg);
    cudaGetSymbolAddress((void**)&pas1, g_as1);  cudaGetSymbolAddress((void**)&pad1, g_ad1);
    cudaGetSymbolAddress((void**)&pas2, g_as2);  cudaGetSymbolAddress((void**)&pad2, g_ad2);
    cudaGetSymbolAddress((void**)&pdinv, g_dinv);
    cudaGetSymbolAddress((void**)&pg1, g_g1);    cudaGetSymbolAddress((void**)&phe1, g_he1);
    cudaGetSymbolAddress((void**)&pg2, g_g2);    cudaGetSymbolAddress((void**)&phekg, g_hekg);
    cudaGetSymbolAddress((void**)&pq, g_q);      cudaGetSymbolAddress((void**)&pk, g_k);
    cudaGetSymbolAddress((void**)&pv, g_v);      cudaGetSymbolAddress((void**)&pao, g_attnout);
    cudaGetSymbolAddress((void**)&pqn, g_qn);    cudaGetSymbolAddress((void**)&pknm, g_knm);
    cudaGetSymbolAddress((void**)&pdsum, g_dsum);
    cudaGetSymbolAddress((void**)&pbcomb, g_bcomb); cudaGetSymbolAddress((void**)&pbfold, g_bfold);
    cudaGetSymbolAddress((void**)&pcnt_t, g_cnt_t); cudaGetSymbolAddress((void**)&pcur_t, g_cur_t);
    cudaGetSymbolAddress((void**)&poff_t, g_off_t); cudaGetSymbolAddress((void**)&psrcs_t, g_srcs_t);
    cudaGetSymbolAddress((void**)&pcnt_e, g_cnt_e); cudaGetSymbolAddress((void**)&pcur_e, g_cur_e);
    cudaGetSymbolAddress((void**)&poff_e, g_off_e); cudaGetSymbolAddress((void**)&psrcs_e, g_srcs_e);

    static cudaStream_t s1 = nullptr, s2 = nullptr;
    static cudaEvent_t evRoot = nullptr, evT = nullptr, evB = nullptr, evQ0 = nullptr, evA0 = nullptr;
    if (!s1) {
        cudaStreamCreateWithFlags(&s1, cudaStreamNonBlocking);
        cudaStreamCreateWithFlags(&s2, cudaStreamNonBlocking);
        cudaEventCreateWithFlags(&evRoot, cudaEventDisableTiming);
        cudaEventCreateWithFlags(&evT, cudaEventDisableTiming);
        cudaEventCreateWithFlags(&evB, cudaEventDisableTiming);
        cudaEventCreateWithFlags(&evQ0, cudaEventDisableTiming);
        cudaEventCreateWithFlags(&evA0, cudaEventDisableTiming);
    }

    const int T = 256;
    const int EB = (EE + T - 1) / T;

    // ===== fork =====
    cudaEventRecord(evRoot, 0);
    cudaStreamWaitEvent(s1, evRoot, 0);
    cudaStreamWaitEvent(s2, evRoot, 0);

    // ----- s1: CSR for TKG graph -----
    cudaMemsetAsync(pcnt_t, 0, NN * sizeof(int), s1);
    cudaMemsetAsync(pcur_t, 0, NN * sizeof(int), s1);
    hist_kernel<<<EB, T, 0, s1>>>(eit, pcnt_t);
    scan_kernel<<<1, 1024, 0, s1>>>(pcnt_t, poff_t);
    scatter_kernel<<<EB, T, 0, s1>>>(eit, poff_t, pcur_t, psrcs_t);
    cudaEventRecord(evT, s1);

    // ----- s2: fold(Wo->fc1) + CSR EKG + GCN branch + K/V projections (+k-norms) -----
    fold_kernel<<<33, T, 0, s2>>>(Wo, bo, fc1_W, fc1_b, pbcomb, pbfold);
    cudaMemsetAsync(pcnt_e, 0, NN * sizeof(int), s2);
    cudaMemsetAsync(pcur_e, 0, NN * sizeof(int), s2);
    cudaMemsetAsync(pknm, 0, 2 * sizeof(float), s2);
    hist_kernel<<<EB, T, 0, s2>>>(eie, pcnt_e);
    scan_kernel<<<1, 1024, 0, s2>>>(pcnt_e, poff_e);
    scatter_kernel<<<EB, T, 0, s2>>>(eie, poff_e, pcur_e, psrcs_e);
    dinv_kernel<<<(NN + T - 1) / T, T, 0, s2>>>(pcnt_e, pdinv);
    gemm64<<<dim3(1, 128), 256, 0, s2>>>(x, nullptr, gcn1_W, nullptr, pg1, nullptr, NN, 64, DIN, 0,
                                         0, nullptr, nullptr, nullptr, nullptr, 0);
    gcn_aggr_csr<<<(NN * 32 + T - 1) / T, T, 0, s2>>>(poff_e, psrcs_e, pg1, pdinv, gcn1_b, phe1);
    gemm64<<<dim3(1, 128), 256, 0, s2>>>(phe1, nullptr, gcn2_W, nullptr, pg2, nullptr, NN, 64, 64, 0,
                                         0, nullptr, nullptr, nullptr, nullptr, 0);
    gcn_aggr_csr<<<(NN * 32 + T - 1) / T, T, 0, s2>>>(poff_e, psrcs_e, pg2, pdinv, gcn2_b, phekg);
    gemm64<<<dim3(1, 128), 256, 0, s2>>>(phekg, nullptr, Wk, bk, pk, pkh, NN, 64, 64, 0,
                                         3, nullptr, nullptr, pknm, nullptr, 0);
    gemm64<<<dim3(1, 128), 256, 0, s2>>>(phekg, nullptr, Wv, bv, pv, pvh, NN, 64, 64, 0,
                                         0, nullptr, nullptr, nullptr, nullptr, 0);
    cudaEventRecord(evB, s2);

    // ----- s0: GAT branch (critical path) -----
    gemm64<<<dim3(2, 128), 256>>>(x, nullptr, gat1_W, nullptr, ph1, nullptr, NN, 128, DIN, 0,
                                  1, gat1_as, gat1_ad, pas1, pad1, 2);
    cudaStreamWaitEvent(0, evT, 0);
    gat_aggr_csr<<<(NN * 2 * 32 + T - 1) / T, T>>>(poff_t, psrcs_t, pas1, pad1, ph1, gat1_b, pht1, 2);
    gemm64<<<dim3(1, 128), 256>>>(pht1, nullptr, gat2_W, nullptr, ph2, nullptr, NN, 64, 128, 0,
                                  1, gat2_as, gat2_ad, pas2, pad2, 1);
    gat_aggr_csr<<<(NN * 32 + T - 1) / T, T>>>(poff_t, psrcs_t, pas2, pad2, ph2, gat2_b, phtkg, 1);
    gemm64<<<dim3(1, 128), 256>>>(phtkg, nullptr, Wq, bq, pq, pqh, NN, 64, 64, 0,
                                  2, nullptr, nullptr, pqn, nullptr, 0);
    cudaMemsetAsync(pdsum, 0, NN * 2 * sizeof(float));
    cudaMemsetAsync(pao, 0, (size_t)NN * 64 * sizeof(float));
    cudaStreamWaitEvent(0, evB, 0);
    // pipelined attention: q-halves
    qk_exp_wmma<<<dim3(64, 64, 2), 256>>>(pqh, pkh, pqn, pknm, pS, pdsum, 0);
    cudaEventRecord(evQ0, 0);
    qk_exp_wmma<<<dim3(64, 64, 2), 256>>>(pqh, pkh, pqn, pknm, pS, pdsum, NN / 2);
    cudaStreamWaitEvent(s1, evQ0, 0);
    av_wmma<<<dim3(32, 4), 256, 0, s1>>>(pS, pvh, pdsum, pao, out_attn, 0);
    cudaEventRecord(evA0, s1);
    av_wmma<<<dim3(32, 4), 256>>>(pS, pvh, pdsum, pao, out_attn, NN / 2);
    cudaStreamWaitEvent(0, evA0, 0);
    // fc1 (+folded Wo) with fused fc2 epilogue -> pred
    gemm64<<<dim3(1, 128), 256>>>(phtkg, pao, pbcomb, pbfold, nullptr, nullptr, NN, 64, 128, 1,
                                  4, fc2_W, fc2_b, out_pred, nullptr, 0);
}